// round 13
// baseline (speedup 1.0000x reference)
#include <cuda_runtime.h>
#include <math.h>

typedef unsigned int u32;

// weight buffer (floats): six small matrices -> smem; Wm1/Wm2/Wm3 stay in GLOBAL (L2-hot)
#define FB_W0  0
#define FB_W1  2048
#define FB_W2  4096
#define FB_W3  6144
#define FB_WA  8192
#define FB_WB  10240
#define FB_SM  12288               // floats copied to smem
#define FB_WM1 12288
#define FB_WM2 16384
#define FB_WM3 20480
#define FB_TOT 28672

#define NWARP  10
#define TSTR   68
#define TFL    (16 * TSTR)          // 1088
#define OSTR   132
#define ARENA  (4 * TFL)            // 4352 floats
#define SMEM_FLOATS (FB_SM + NWARP * ARENA)    // 55808
#define SMEM_BYTES  (SMEM_FLOATS * 4)          // 223232

__device__ float g_cst;
__device__ float g_wbuf[FB_TOT];

__device__ __forceinline__ u32 tf32(float f) {
    u32 u; asm("cvt.rna.tf32.f32 %0,%1;" : "=r"(u) : "f"(f)); return u;
}
__device__ __forceinline__ float uaf(u32 u) { return __uint_as_float(u); }

__device__ __forceinline__ void mma_t(float* d, u32 a0, u32 a1, u32 a2, u32 a3,
                                      u32 b0, u32 b1) {
    asm("mma.sync.aligned.m16n8k8.row.col.f32.tf32.tf32.f32 "
        "{%0,%1,%2,%3},{%4,%5,%6,%7},{%8,%9},{%0,%1,%2,%3};"
        : "+f"(d[0]), "+f"(d[1]), "+f"(d[2]), "+f"(d[3])
        : "r"(a0), "r"(a1), "r"(a2), "r"(a3), "r"(b0), "r"(b1));
}
__device__ __forceinline__ void ldsm4(uint4& d, u32 addr) {
    asm volatile("ldmatrix.sync.aligned.m8n8.x4.shared.b16 {%0,%1,%2,%3}, [%4];"
        : "=r"(d.x), "=r"(d.y), "=r"(d.z), "=r"(d.w) : "r"(addr));
}
__device__ __forceinline__ u32 cvta_smem(const void* p) {
    u32 a; asm("{ .reg .u64 t; cvta.to.shared.u64 t, %1; cvt.u32.u64 %0, t; }"
               : "=r"(a) : "l"(p)); return a;
}

// acc[4*NT] += T[16x64] @ W(smem) ; A frags via ldmatrix
template<int NT>
__device__ __forceinline__ void gemmL_s(float* acc, u32 Ta, const float* W, int lane) {
#pragma unroll
    for (int k8 = 0; k8 < 8; k8++) {
        uint4 f; ldsm4(f, Ta + k8 * 32);
        u32 a0 = tf32(uaf(f.x)), a1 = tf32(uaf(f.y));
        u32 a2 = tf32(uaf(f.z)), a3 = tf32(uaf(f.w));
        const float* wp = W + k8 * NT * 64 + 2 * lane;
#pragma unroll
        for (int nt = 0; nt < NT; nt++) {
            uint2 b = *(const uint2*)(wp + nt * 64);
            mma_t(acc + 4 * nt, a0, a1, a2, a3, b.x, b.y);
        }
    }
}
// same but W read from GLOBAL via __ldg (Wm1/Wm2/Wm3, L2-hot)
template<int NT>
__device__ __forceinline__ void gemmL_g(float* acc, u32 Ta, const float* W, int lane) {
#pragma unroll
    for (int k8 = 0; k8 < 8; k8++) {
        uint4 f; ldsm4(f, Ta + k8 * 32);
        u32 a0 = tf32(uaf(f.x)), a1 = tf32(uaf(f.y));
        u32 a2 = tf32(uaf(f.z)), a3 = tf32(uaf(f.w));
        const float* wp = W + k8 * NT * 64 + 2 * lane;
#pragma unroll
        for (int nt = 0; nt < NT; nt++) {
            uint2 b = __ldg((const uint2*)(wp + nt * 64));
            mma_t(acc + 4 * nt, a0, a1, a2, a3, b.x, b.y);
        }
    }
}

// ---------------- prep ----------------
__global__ void prep_kernel(const float* __restrict__ w0, const float* __restrict__ w1,
                            const float* __restrict__ w2, const float* __restrict__ w3,
                            const float* __restrict__ Wl0, const float* __restrict__ Wl1,
                            const float* __restrict__ Wm1, const float* __restrict__ Wm2,
                            const float* __restrict__ Wm3,
                            const float* __restrict__ Wf0, const float* __restrict__ Wf1) {
    if (blockIdx.x == 0) {
        const int   N = 20000;
        const float h = 24.0f / 20000.0f;
        float local = 0.0f;
        for (int i = threadIdx.x; i <= N; i += blockDim.x) {
            float z   = -12.0f + h * (float)i;
            float s   = z / (1.0f + __expf(-z));
            float phi = __expf(-0.5f * z * z) * 0.3989422804014327f;
            float f   = s * s * phi;
            if (i == 0 || i == N) f *= 0.5f;
            local += f;
        }
        __shared__ float red[256];
        red[threadIdx.x] = local;
        __syncthreads();
        for (int s = 128; s > 0; s >>= 1) {
            if (threadIdx.x < s) red[threadIdx.x] += red[threadIdx.x + s];
            __syncthreads();
        }
        if (threadIdx.x == 0) g_cst = rsqrtf(red[0] * h);
    }

    int tid = blockIdx.x * blockDim.x + threadIdx.x;
    if (tid >= FB_TOT) return;
    const float INV_S3 = 0.57735026918962576f;
    const float WSCALE = 0.125f * 0.125f * 0.17677669529663687f;

    int mbase, N;
    if (tid < FB_SM)           { mbase = (tid / 2048) * 2048; N = 32; }
    else if (tid < FB_WM2)     { mbase = FB_WM1; N = 64; }
    else if (tid < FB_WM3)     { mbase = FB_WM2; N = 64; }
    else                       { mbase = FB_WM3; N = 128; }
    int idx = tid - mbase;
    int g = idx >> 6, pos = idx & 63, l = pos >> 1, hh = pos & 1;
    int ntn = N >> 3, k8 = g / ntn, n8 = g % ntn;
    int row = k8 * 8 + (l & 3) + 4 * hh;   // K index
    int col = n8 * 8 + (l >> 2);           // N index

    float v;
    if (tid < 2048)            v = w0[row * 32 + col];
    else if (tid < 4096)       v = w1[row * 32 + col] * INV_S3;
    else if (tid < 6144)       v = w2[row * 32 + col];
    else if (tid < 8192)       v = w3[row * 32 + col];
    else if (tid < FB_SM) {
        const float* L = (tid < 10240) ? Wl0 : Wl1;
        const float* F = (tid < 10240) ? Wf0 : Wf1;
        float acc = 0.0f;
        for (int w = 0; w < 32; w++) acc = fmaf(L[row * 32 + w], F[w * 32 + col], acc);
        v = acc * WSCALE;
    }
    else if (tid < FB_WM2)     v = Wm1[row * 64 + col] * 0.125f;
    else if (tid < FB_WM3)     v = Wm2[row * 64 + col] * 0.125f;
    else                       v = Wm3[row * 128 + col] * 0.125f;
    g_wbuf[tid] = __uint_as_float(tf32(v));
}

// ---------------- main ----------------
__global__ __launch_bounds__(32 * NWARP, 1)
void tp_mma_kernel(const float* __restrict__ x1a, const float* __restrict__ x1b,
                   const float4* __restrict__ x2, const float* __restrict__ scalars,
                   float* __restrict__ out, int nrows) {
    extern __shared__ float smem[];
    {
        const float4* src = (const float4*)g_wbuf;
        float4* dst = (float4*)smem;
        for (int i = threadIdx.x; i < FB_SM / 4; i += 32 * NWARP) dst[i] = src[i];
    }
    __syncthreads();
    const float cst = g_cst;
    const float* wm1g = g_wbuf + FB_WM1;
    const float* wm2g = g_wbuf + FB_WM2;
    const float* wm3g = g_wbuf + FB_WM3;

    const int lane = threadIdx.x & 31, wid = threadIdx.x >> 5;
    const int r4 = lane >> 2, m4 = lane & 3;

    float* A0 = smem + FB_SM + wid * ARENA;
    float* A1 = A0 + TFL;
    float* A2 = A1 + TFL;
    float* A3 = A2 + TFL;

    // ldmatrix per-lane fragment address offset
    const int lrow = (lane & 7) | (((lane >> 3) & 1) << 3);
    const int lcol = (lane >> 4) << 2;
    const u32 fragoff = (u32)(lrow * TSTR + lcol) * 4u;
    const u32 A0f = cvta_smem(A0) + fragoff;
    const u32 A1f = A0f + TFL * 4;
    const u32 A2f = A1f + TFL * 4;
    const u32 A3f = A2f + TFL * 4;

    const int gw = blockIdx.x * NWARP + wid, gwn = gridDim.x * NWARP;
    const int ntiles = nrows >> 4;

    for (int t = gw; t < ntiles; t += gwn) {
        const int base = t * 16;

        // ---- stage scalars (fp32) ----
#pragma unroll
        for (int j = 0; j < 8; j++) {
            int row = r4 + 8 * (j & 1), f4 = m4 + 4 * (j >> 1);
            *(float4*)&A0[row * TSTR + 4 * f4] =
                ((const float4*)scalars)[(base + row) * 16 + f4];
        }
        __syncwarp();

        // ---- MLP GEMM1 -> silu -> GEMM2 -> silu -> GEMM3 (weights via L2) ----
        float h[32];
#pragma unroll
        for (int i = 0; i < 32; i++) h[i] = 0.f;
        gemmL_g<8>(h, A0f, wm1g, lane);
        __syncwarp();
#pragma unroll
        for (int nt = 0; nt < 8; nt++) {
            float a = h[4 * nt],     b = h[4 * nt + 1];
            float c = h[4 * nt + 2], d = h[4 * nt + 3];
            float2 lo = {cst * a / (1.f + __expf(-a)), cst * b / (1.f + __expf(-b))};
            float2 hi = {cst * c / (1.f + __expf(-c)), cst * d / (1.f + __expf(-d))};
            *(float2*)&A0[r4 * TSTR + nt * 8 + 2 * m4]       = lo;
            *(float2*)&A0[(r4 + 8) * TSTR + nt * 8 + 2 * m4] = hi;
        }
        __syncwarp();
#pragma unroll
        for (int i = 0; i < 32; i++) h[i] = 0.f;
        gemmL_g<8>(h, A0f, wm2g, lane);
        __syncwarp();
#pragma unroll
        for (int nt = 0; nt < 8; nt++) {
            float a = h[4 * nt],     b = h[4 * nt + 1];
            float c = h[4 * nt + 2], d = h[4 * nt + 3];
            float2 lo = {cst * a / (1.f + __expf(-a)), cst * b / (1.f + __expf(-b))};
            float2 hi = {cst * c / (1.f + __expf(-c)), cst * d / (1.f + __expf(-d))};
            *(float2*)&A0[r4 * TSTR + nt * 8 + 2 * m4]       = lo;
            *(float2*)&A0[(r4 + 8) * TSTR + nt * 8 + 2 * m4] = hi;
        }
        __syncwarp();
        float wt[64];
#pragma unroll
        for (int i = 0; i < 64; i++) wt[i] = 0.f;
        gemmL_g<16>(wt, A0f, wm3g, lane);
        __syncwarp();

        // ---- stage x1: head -> s0 (A0), tail -> s1 planes (A1..A3), all float4 ----
#pragma unroll
        for (int it = 0; it < 8; it++) {
            int fid = it * 32 + lane;
            int row = fid >> 4, within = fid & 15;
            int arr = within >> 3, j = within & 7;
            const float4* src = arr ? (const float4*)x1b : (const float4*)x1a;
            float4 v = src[(base + row) * 32 + j];
            *(float4*)&A0[row * TSTR + arr * 32 + 4 * j] = v;
        }
#pragma unroll
        for (int it = 0; it < 8; it++) {
            int sid = it * 32 + lane;
            int row = sid >> 4, within = sid & 15;
            int arr = within >> 3, q = within & 7;
            const float4* src = arr ? (const float4*)x1b : (const float4*)x1a;
            int p = (base + row) * 32 + 8 + 3 * q;
            float4 v0 = src[p], v1 = src[p + 1], v2 = src[p + 2];
            int off = row * TSTR + arr * 32 + 4 * q;
            *(float4*)&A1[off] = make_float4(v0.x, v0.w, v1.z, v2.y);
            *(float4*)&A2[off] = make_float4(v0.y, v1.x, v1.w, v2.z);
            *(float4*)&A3[off] = make_float4(v0.z, v1.y, v2.x, v2.w);
        }
        __syncwarp();

        // ---- y direct from global (L1-hot) ----
        float4 yA = __ldg(&x2[base + r4]);
        float4 yB = __ldg(&x2[base + r4 + 8]);
        const float y0A = yA.x, yA1 = yA.y, yA2 = yA.z, yA3 = yA.w;
        const float y0B = yB.x, yB1 = yB.y, yB2 = yB.z, yB3 = yB.w;

        // ---- G4/G5: R0 = s0@w0, Pp = s0@w2 (shared A frags via ldmatrix) ----
        float R0[16], Pp[16], R1[16];
#pragma unroll
        for (int i = 0; i < 16; i++) { R0[i] = 0.f; Pp[i] = 0.f; R1[i] = 0.f; }
#pragma unroll
        for (int k8 = 0; k8 < 8; k8++) {
            uint4 f; ldsm4(f, A0f + k8 * 32);
            u32 a0 = tf32(uaf(f.x)), a1 = tf32(uaf(f.y));
            u32 a2 = tf32(uaf(f.z)), a3 = tf32(uaf(f.w));
            const float* w0p = smem + FB_W0 + k8 * 4 * 64 + 2 * lane;
            const float* w2p = smem + FB_W2 + k8 * 4 * 64 + 2 * lane;
#pragma unroll
            for (int nt = 0; nt < 4; nt++) {
                uint2 b0 = *(const uint2*)(w0p + nt * 64);
                mma_t(R0 + 4 * nt, a0, a1, a2, a3, b0.x, b0.y);
                uint2 b2 = *(const uint2*)(w2p + nt * 64);
                mma_t(Pp + 4 * nt, a0, a1, a2, a3, b2.x, b2.y);
            }
        }

        // ---- G6+G7 fused: one set of plane ldsm feeds t1@w1 AND s1k@w3 ----
        float Q[48];
#pragma unroll
        for (int i = 0; i < 48; i++) Q[i] = 0.f;
#pragma unroll
        for (int k8 = 0; k8 < 8; k8++) {
            uint4 f1; ldsm4(f1, A1f + k8 * 32);
            uint4 f2; ldsm4(f2, A2f + k8 * 32);
            uint4 f3; ldsm4(f3, A3f + k8 * 32);
            // t1 frags (fp32 fma, then cvt)
            float t0  = uaf(f1.x) * yA1 + uaf(f2.x) * yA2 + uaf(f3.x) * yA3;
            float t1v = uaf(f1.y) * yB1 + uaf(f2.y) * yB2 + uaf(f3.y) * yB3;
            float t2  = uaf(f1.z) * yA1 + uaf(f2.z) * yA2 + uaf(f3.z) * yA3;
            float t3  = uaf(f1.w) * yB1 + uaf(f2.w) * yB2 + uaf(f3.w) * yB3;
            u32 c0 = tf32(t0), c1 = tf32(t1v), c2 = tf32(t2), c3 = tf32(t3);
            const float* w1p = smem + FB_W1 + k8 * 4 * 64 + 2 * lane;
#pragma unroll
            for (int nt = 0; nt < 4; nt++) {
                uint2 b = *(const uint2*)(w1p + nt * 64);
                mma_t(R1 + 4 * nt, c0, c1, c2, c3, b.x, b.y);
            }
            // plane frags for w3
            u32 p0 = tf32(uaf(f1.x)), p1 = tf32(uaf(f1.y)), p2 = tf32(uaf(f1.z)), p3 = tf32(uaf(f1.w));
            u32 q0 = tf32(uaf(f2.x)), q1 = tf32(uaf(f2.y)), q2 = tf32(uaf(f2.z)), q3 = tf32(uaf(f2.w));
            u32 s0 = tf32(uaf(f3.x)), s1 = tf32(uaf(f3.y)), s2 = tf32(uaf(f3.z)), s3 = tf32(uaf(f3.w));
            const float* w3p = smem + FB_W3 + k8 * 4 * 64 + 2 * lane;
#pragma unroll
            for (int nt = 0; nt < 4; nt++) {
                uint2 b = *(const uint2*)(w3p + nt * 64);
                mma_t(Q + 4 * nt,      p0, p1, p2, p3, b.x, b.y);
                mma_t(Q + 16 + 4 * nt, q0, q1, q2, q3, b.x, b.y);
                mma_t(Q + 32 + 4 * nt, s0, s1, s2, s3, b.x, b.y);
            }
        }
        __syncwarp();   // all s0/s1 reads done -> overlay m0/m1k

        // ---- m0 build -> A0 (float2 stores) ----
#pragma unroll
        for (int nt = 0; nt < 4; nt++) {
            int u = nt * 8 + 2 * m4;
            *(float2*)&A0[r4 * TSTR + u] =
                make_float2(y0A * R0[4 * nt] * wt[4 * nt], y0A * R0[4 * nt + 1] * wt[4 * nt + 1]);
            *(float2*)&A0[(r4 + 8) * TSTR + u] =
                make_float2(y0B * R0[4 * nt + 2] * wt[4 * nt + 2], y0B * R0[4 * nt + 3] * wt[4 * nt + 3]);
            int wi = 4 * (nt + 4);
            *(float2*)&A0[r4 * TSTR + 32 + u] =
                make_float2(R1[4 * nt] * wt[wi], R1[4 * nt + 1] * wt[wi + 1]);
            *(float2*)&A0[(r4 + 8) * TSTR + 32 + u] =
                make_float2(R1[4 * nt + 2] * wt[wi + 2], R1[4 * nt + 3] * wt[wi + 3]);
        }

        // ---- m1k build -> A1..A3 (float2 stores) ----
#pragma unroll
        for (int k = 0; k < 3; k++) {
            float* Tk = (k == 0) ? A1 : ((k == 1) ? A2 : A3);
            float ykA = (k == 0) ? yA1 : ((k == 1) ? yA2 : yA3);
            float ykB = (k == 0) ? yB1 : ((k == 1) ? yB2 : yB3);
#pragma unroll
            for (int nt = 0; nt < 4; nt++) {
                int wi = 4 * (nt + 8), wj = 4 * (nt + 12);
                int u = nt * 8 + 2 * m4;
                *(float2*)&Tk[r4 * TSTR + u] =
                    make_float2(ykA * Pp[4 * nt] * wt[wi], ykA * Pp[4 * nt + 1] * wt[wi + 1]);
                *(float2*)&Tk[(r4 + 8) * TSTR + u] =
                    make_float2(ykB * Pp[4 * nt + 2] * wt[wi + 2], ykB * Pp[4 * nt + 3] * wt[wi + 3]);
                *(float2*)&Tk[r4 * TSTR + 32 + u] =
                    make_float2(y0A * Q[16 * k + 4 * nt] * wt[wj], y0A * Q[16 * k + 4 * nt + 1] * wt[wj + 1]);
                *(float2*)&Tk[(r4 + 8) * TSTR + 32 + u] =
                    make_float2(y0B * Q[16 * k + 4 * nt + 2] * wt[wj + 2], y0B * Q[16 * k + 4 * nt + 3] * wt[wj + 3]);
            }
        }
        __syncwarp();

        // ---- G8: O0 = m0@WA ; G9: Ok = m1k@WB (B shared, plane ldsm) ----
        float O0[16];
#pragma unroll
        for (int i = 0; i < 16; i++) O0[i] = 0.f;
        gemmL_s<4>(O0, A0f, smem + FB_WA, lane);

        float O[48];
#pragma unroll
        for (int i = 0; i < 48; i++) O[i] = 0.f;
#pragma unroll
        for (int k8 = 0; k8 < 8; k8++) {
            uint4 f1; ldsm4(f1, A1f + k8 * 32);
            uint4 f2; ldsm4(f2, A2f + k8 * 32);
            uint4 f3; ldsm4(f3, A3f + k8 * 32);
            u32 p0 = tf32(uaf(f1.x)), p1 = tf32(uaf(f1.y)), p2 = tf32(uaf(f1.z)), p3 = tf32(uaf(f1.w));
            u32 q0 = tf32(uaf(f2.x)), q1 = tf32(uaf(f2.y)), q2 = tf32(uaf(f2.z)), q3 = tf32(uaf(f2.w));
            u32 s0 = tf32(uaf(f3.x)), s1 = tf32(uaf(f3.y)), s2 = tf32(uaf(f3.z)), s3 = tf32(uaf(f3.w));
            const float* wbp = smem + FB_WB + k8 * 4 * 64 + 2 * lane;
#pragma unroll
            for (int nt = 0; nt < 4; nt++) {
                uint2 b = *(const uint2*)(wbp + nt * 64);
                mma_t(O + 4 * nt,      p0, p1, p2, p3, b.x, b.y);
                mma_t(O + 16 + 4 * nt, q0, q1, q2, q3, b.x, b.y);
                mma_t(O + 32 + 4 * nt, s0, s1, s2, s3, b.x, b.y);
            }
        }
        __syncwarp();   // m reads done -> overlay out staging on A0/A1

        // ---- stage outputs (OB = A0, stride OSTR) ----
        float* OB = A0;
#pragma unroll
        for (int nt = 0; nt < 4; nt++) {
            int u = nt * 8 + 2 * m4;
            *(float2*)&OB[r4 * OSTR + u]       = make_float2(O0[4 * nt],     O0[4 * nt + 1]);
            *(float2*)&OB[(r4 + 8) * OSTR + u] = make_float2(O0[4 * nt + 2], O0[4 * nt + 3]);
#pragma unroll
            for (int k = 0; k < 3; k++) {
                int c = 32 + 3 * u + k;
                OB[r4 * OSTR + c]           = O[16 * k + 4 * nt];
                OB[r4 * OSTR + c + 3]       = O[16 * k + 4 * nt + 1];
                OB[(r4 + 8) * OSTR + c]     = O[16 * k + 4 * nt + 2];
                OB[(r4 + 8) * OSTR + c + 3] = O[16 * k + 4 * nt + 3];
            }
        }
        __syncwarp();
#pragma unroll
        for (int rr = 0; rr < 16; rr++)
            ((float4*)out)[(base + rr) * 32 + lane] = *(const float4*)&OB[rr * OSTR + 4 * lane];
        __syncwarp();
    }
}

// ---------------- launch ----------------
extern "C" void kernel_launch(void* const* d_in, const int* in_sizes, int n_in,
                              void* d_out, int out_size) {
    const float* x1a     = (const float*)d_in[0];
    const float* x1b     = (const float*)d_in[1];
    const float* x2      = (const float*)d_in[2];
    const float* scalars = (const float*)d_in[3];
    const float* w0      = (const float*)d_in[4];
    const float* w1      = (const float*)d_in[5];
    const float* w2      = (const float*)d_in[6];
    const float* w3      = (const float*)d_in[7];
    const float* Wl0     = (const float*)d_in[8];
    const float* Wl1     = (const float*)d_in[9];
    const float* Wm1     = (const float*)d_in[10];
    const float* Wm2     = (const float*)d_in[11];
    const float* Wm3     = (const float*)d_in[12];
    const float* Wf0     = (const float*)d_in[13];
    const float* Wf1     = (const float*)d_in[14];
    int n = in_sizes[0] / 128;

    cudaFuncSetAttribute(tp_mma_kernel, cudaFuncAttributeMaxDynamicSharedMemorySize, SMEM_BYTES);

    prep_kernel<<<112, 256>>>(w0, w1, w2, w3, Wl0, Wl1, Wm1, Wm2, Wm3, Wf0, Wf1);
    tp_mma_kernel<<<148, 32 * NWARP, SMEM_BYTES>>>(x1a, x1b, (const float4*)x2, scalars,
                                                   (float*)d_out, n);
}

// round 14
// speedup vs baseline: 1.0696x; 1.0696x over previous
#include <cuda_runtime.h>
#include <math.h>

typedef unsigned int u32;

// weight buffer (floats): six small matrices -> smem; Wm1/Wm2/Wm3 stay in GLOBAL (L2-hot)
#define FB_W0  0
#define FB_W1  2048
#define FB_W2  4096
#define FB_W3  6144
#define FB_WA  8192
#define FB_WB  10240
#define FB_SM  12288               // floats copied to smem
#define FB_WM1 12288
#define FB_WM2 16384
#define FB_WM3 20480
#define FB_TOT 28672

#define NWARP  10
#define TSTR   68
#define TFL    (16 * TSTR)          // 1088
#define OSTR   132
#define ARENA  (4 * TFL)            // 4352 floats
#define SMEM_FLOATS (FB_SM + NWARP * ARENA)    // 55808
#define SMEM_BYTES  (SMEM_FLOATS * 4)          // 223232

__device__ float g_cst;
__device__ float g_wbuf[FB_TOT];

__device__ __forceinline__ u32 tf32(float f) {
    u32 u; asm("cvt.rna.tf32.f32 %0,%1;" : "=r"(u) : "f"(f)); return u;
}
__device__ __forceinline__ void mma_t(float* d, u32 a0, u32 a1, u32 a2, u32 a3,
                                      u32 b0, u32 b1) {
    asm("mma.sync.aligned.m16n8k8.row.col.f32.tf32.tf32.f32 "
        "{%0,%1,%2,%3},{%4,%5,%6,%7},{%8,%9},{%0,%1,%2,%3};"
        : "+f"(d[0]), "+f"(d[1]), "+f"(d[2]), "+f"(d[3])
        : "r"(a0), "r"(a1), "r"(a2), "r"(a3), "r"(b0), "r"(b1));
}

// acc[4*NT] += T[16x64] @ W(smem) ; single-tf32 A and W
template<int NT>
__device__ __forceinline__ void gemm16s(float* acc, const float* T, const float* W,
                                        int r4, int m4, int lane) {
#pragma unroll
    for (int k8 = 0; k8 < 8; k8++) {
        const float* ap = T + r4 * TSTR + k8 * 8 + m4;
        u32 a0 = tf32(ap[0]);
        u32 a1 = tf32(ap[8 * TSTR]);
        u32 a2 = tf32(ap[4]);
        u32 a3 = tf32(ap[8 * TSTR + 4]);
        const float* wp = W + k8 * NT * 64 + 2 * lane;
#pragma unroll
        for (int nt = 0; nt < NT; nt++) {
            uint2 b = *(const uint2*)(wp + nt * 64);
            mma_t(acc + 4 * nt, a0, a1, a2, a3, b.x, b.y);
        }
    }
}

// same but W read from GLOBAL via __ldg (Wm1/Wm2/Wm3, L2-hot)
template<int NT>
__device__ __forceinline__ void gemm16g(float* acc, const float* T, const float* W,
                                        int r4, int m4, int lane) {
#pragma unroll
    for (int k8 = 0; k8 < 8; k8++) {
        const float* ap = T + r4 * TSTR + k8 * 8 + m4;
        u32 a0 = tf32(ap[0]);
        u32 a1 = tf32(ap[8 * TSTR]);
        u32 a2 = tf32(ap[4]);
        u32 a3 = tf32(ap[8 * TSTR + 4]);
        const float* wp = W + k8 * NT * 64 + 2 * lane;
#pragma unroll
        for (int nt = 0; nt < NT; nt++) {
            uint2 b = __ldg((const uint2*)(wp + nt * 64));
            mma_t(acc + 4 * nt, a0, a1, a2, a3, b.x, b.y);
        }
    }
}

// ---------------- prep ----------------
__global__ void prep_kernel(const float* __restrict__ w0, const float* __restrict__ w1,
                            const float* __restrict__ w2, const float* __restrict__ w3,
                            const float* __restrict__ Wl0, const float* __restrict__ Wl1,
                            const float* __restrict__ Wm1, const float* __restrict__ Wm2,
                            const float* __restrict__ Wm3,
                            const float* __restrict__ Wf0, const float* __restrict__ Wf1) {
    if (blockIdx.x == 0) {
        const int   N = 20000;
        const float h = 24.0f / 20000.0f;
        float local = 0.0f;
        for (int i = threadIdx.x; i <= N; i += blockDim.x) {
            float z   = -12.0f + h * (float)i;
            float s   = z / (1.0f + __expf(-z));
            float phi = __expf(-0.5f * z * z) * 0.3989422804014327f;
            float f   = s * s * phi;
            if (i == 0 || i == N) f *= 0.5f;
            local += f;
        }
        __shared__ float red[256];
        red[threadIdx.x] = local;
        __syncthreads();
        for (int s = 128; s > 0; s >>= 1) {
            if (threadIdx.x < s) red[threadIdx.x] += red[threadIdx.x + s];
            __syncthreads();
        }
        if (threadIdx.x == 0) g_cst = rsqrtf(red[0] * h);
    }

    int tid = blockIdx.x * blockDim.x + threadIdx.x;
    if (tid >= FB_TOT) return;
    const float INV_S3 = 0.57735026918962576f;
    const float WSCALE = 0.125f * 0.125f * 0.17677669529663687f;

    int mbase, N;
    if (tid < FB_SM)           { mbase = (tid / 2048) * 2048; N = 32; }
    else if (tid < FB_WM2)     { mbase = FB_WM1; N = 64; }
    else if (tid < FB_WM3)     { mbase = FB_WM2; N = 64; }
    else                       { mbase = FB_WM3; N = 128; }
    int idx = tid - mbase;
    int g = idx >> 6, pos = idx & 63, l = pos >> 1, hh = pos & 1;
    int ntn = N >> 3, k8 = g / ntn, n8 = g % ntn;
    int row = k8 * 8 + (l & 3) + 4 * hh;   // K index
    int col = n8 * 8 + (l >> 2);           // N index

    float v;
    if (tid < 2048)            v = w0[row * 32 + col];
    else if (tid < 4096)       v = w1[row * 32 + col] * INV_S3;
    else if (tid < 6144)       v = w2[row * 32 + col];
    else if (tid < 8192)       v = w3[row * 32 + col];
    else if (tid < FB_SM) {
        const float* L = (tid < 10240) ? Wl0 : Wl1;
        const float* F = (tid < 10240) ? Wf0 : Wf1;
        float acc = 0.0f;
        for (int w = 0; w < 32; w++) acc = fmaf(L[row * 32 + w], F[w * 32 + col], acc);
        v = acc * WSCALE;
    }
    else if (tid < FB_WM2)     v = Wm1[row * 64 + col] * 0.125f;
    else if (tid < FB_WM3)     v = Wm2[row * 64 + col] * 0.125f;
    else                       v = Wm3[row * 128 + col] * 0.125f;
    g_wbuf[tid] = __uint_as_float(tf32(v));
}

// ---------------- main ----------------
__global__ __launch_bounds__(32 * NWARP, 1)
void tp_mma_kernel(const float* __restrict__ x1a, const float* __restrict__ x1b,
                   const float4* __restrict__ x2, const float* __restrict__ scalars,
                   float* __restrict__ out, int nrows) {
    extern __shared__ float smem[];
    {
        const float4* src = (const float4*)g_wbuf;
        float4* dst = (float4*)smem;
        for (int i = threadIdx.x; i < FB_SM / 4; i += 32 * NWARP) dst[i] = src[i];
    }
    __syncthreads();
    const float cst = g_cst;
    const float* wm1g = g_wbuf + FB_WM1;
    const float* wm2g = g_wbuf + FB_WM2;
    const float* wm3g = g_wbuf + FB_WM3;

    const int lane = threadIdx.x & 31, wid = threadIdx.x >> 5;
    const int r4 = lane >> 2, m4 = lane & 3;

    float* A0 = smem + FB_SM + wid * ARENA;
    float* A1 = A0 + TFL;
    float* A2 = A1 + TFL;
    float* A3 = A2 + TFL;

    const int gw = blockIdx.x * NWARP + wid, gwn = gridDim.x * NWARP;
    const int ntiles = nrows >> 4;

    for (int t = gw; t < ntiles; t += gwn) {
        const int base = t * 16;

        // ---- stage scalars (fp32) ----
#pragma unroll
        for (int j = 0; j < 8; j++) {
            int row = r4 + 8 * (j & 1), f4 = m4 + 4 * (j >> 1);
            *(float4*)&A0[row * TSTR + 4 * f4] =
                ((const float4*)scalars)[(base + row) * 16 + f4];
        }
        __syncwarp();

        // ---- MLP GEMM1 -> silu -> GEMM2 -> silu -> GEMM3 (weights via L2) ----
        float h[32];
#pragma unroll
        for (int i = 0; i < 32; i++) h[i] = 0.f;
        gemm16g<8>(h, A0, wm1g, r4, m4, lane);
        __syncwarp();
#pragma unroll
        for (int nt = 0; nt < 8; nt++) {
            float a = h[4 * nt],     b = h[4 * nt + 1];
            float c = h[4 * nt + 2], d = h[4 * nt + 3];
            float2 lo = {cst * a / (1.f + __expf(-a)), cst * b / (1.f + __expf(-b))};
            float2 hi = {cst * c / (1.f + __expf(-c)), cst * d / (1.f + __expf(-d))};
            *(float2*)&A0[r4 * TSTR + nt * 8 + 2 * m4]       = lo;
            *(float2*)&A0[(r4 + 8) * TSTR + nt * 8 + 2 * m4] = hi;
        }
        __syncwarp();
#pragma unroll
        for (int i = 0; i < 32; i++) h[i] = 0.f;
        gemm16g<8>(h, A0, wm2g, r4, m4, lane);
        __syncwarp();
#pragma unroll
        for (int nt = 0; nt < 8; nt++) {
            float a = h[4 * nt],     b = h[4 * nt + 1];
            float c = h[4 * nt + 2], d = h[4 * nt + 3];
            float2 lo = {cst * a / (1.f + __expf(-a)), cst * b / (1.f + __expf(-b))};
            float2 hi = {cst * c / (1.f + __expf(-c)), cst * d / (1.f + __expf(-d))};
            *(float2*)&A0[r4 * TSTR + nt * 8 + 2 * m4]       = lo;
            *(float2*)&A0[(r4 + 8) * TSTR + nt * 8 + 2 * m4] = hi;
        }
        __syncwarp();
        float wt[64];
#pragma unroll
        for (int i = 0; i < 64; i++) wt[i] = 0.f;
        gemm16g<16>(wt, A0, wm3g, r4, m4, lane);
        __syncwarp();

        // ---- stage x1: head -> s0 (A0), tail -> s1 planes (A1..A3), all float4 ----
#pragma unroll
        for (int it = 0; it < 8; it++) {
            int fid = it * 32 + lane;
            int row = fid >> 4, within = fid & 15;
            int arr = within >> 3, j = within & 7;
            const float4* src = arr ? (const float4*)x1b : (const float4*)x1a;
            float4 v = src[(base + row) * 32 + j];
            *(float4*)&A0[row * TSTR + arr * 32 + 4 * j] = v;
        }
#pragma unroll
        for (int it = 0; it < 8; it++) {
            int sid = it * 32 + lane;
            int row = sid >> 4, within = sid & 15;
            int arr = within >> 3, q = within & 7;
            const float4* src = arr ? (const float4*)x1b : (const float4*)x1a;
            int p = (base + row) * 32 + 8 + 3 * q;
            float4 v0 = src[p], v1 = src[p + 1], v2 = src[p + 2];
            int off = row * TSTR + arr * 32 + 4 * q;
            *(float4*)&A1[off] = make_float4(v0.x, v0.w, v1.z, v2.y);
            *(float4*)&A2[off] = make_float4(v0.y, v1.x, v1.w, v2.z);
            *(float4*)&A3[off] = make_float4(v0.z, v1.y, v2.x, v2.w);
        }
        __syncwarp();

        // ---- y direct from global (L1-hot) ----
        float4 yA = __ldg(&x2[base + r4]);
        float4 yB = __ldg(&x2[base + r4 + 8]);
        const float y0A = yA.x, yA1 = yA.y, yA2 = yA.z, yA3 = yA.w;
        const float y0B = yB.x, yB1 = yB.y, yB2 = yB.z, yB3 = yB.w;

        // ---- G4/G5: R0 = s0@w0, Pp = s0@w2 (shared A frags) ----
        float R0[16], Pp[16], R1[16];
#pragma unroll
        for (int i = 0; i < 16; i++) { R0[i] = 0.f; Pp[i] = 0.f; R1[i] = 0.f; }
#pragma unroll
        for (int k8 = 0; k8 < 8; k8++) {
            const float* ap = A0 + r4 * TSTR + k8 * 8 + m4;
            u32 a0 = tf32(ap[0]);
            u32 a1 = tf32(ap[8 * TSTR]);
            u32 a2 = tf32(ap[4]);
            u32 a3 = tf32(ap[8 * TSTR + 4]);
            const float* w0p = smem + FB_W0 + k8 * 4 * 64 + 2 * lane;
            const float* w2p = smem + FB_W2 + k8 * 4 * 64 + 2 * lane;
#pragma unroll
            for (int nt = 0; nt < 4; nt++) {
                uint2 b0 = *(const uint2*)(w0p + nt * 64);
                mma_t(R0 + 4 * nt, a0, a1, a2, a3, b0.x, b0.y);
                uint2 b2 = *(const uint2*)(w2p + nt * 64);
                mma_t(Pp + 4 * nt, a0, a1, a2, a3, b2.x, b2.y);
            }
        }

        // ---- G6+G7 fused: one set of plane LDS feeds t1@w1 AND s1k@w3 ----
        float Q[48];
#pragma unroll
        for (int i = 0; i < 48; i++) Q[i] = 0.f;
#pragma unroll
        for (int k8 = 0; k8 < 8; k8++) {
            int o = r4 * TSTR + k8 * 8 + m4;
            float p0f = A1[o], p2f = A1[o + 4], p1f = A1[o + 8 * TSTR], p3f = A1[o + 8 * TSTR + 4];
            float q0f = A2[o], q2f = A2[o + 4], q1f = A2[o + 8 * TSTR], q3f = A2[o + 8 * TSTR + 4];
            float s0f = A3[o], s2f = A3[o + 4], s1f = A3[o + 8 * TSTR], s3f = A3[o + 8 * TSTR + 4];
            // t1 frags (fp32 fma, then cvt)
            u32 c0 = tf32(p0f * yA1 + q0f * yA2 + s0f * yA3);
            u32 c1 = tf32(p1f * yB1 + q1f * yB2 + s1f * yB3);
            u32 c2 = tf32(p2f * yA1 + q2f * yA2 + s2f * yA3);
            u32 c3 = tf32(p3f * yB1 + q3f * yB2 + s3f * yB3);
            const float* w1p = smem + FB_W1 + k8 * 4 * 64 + 2 * lane;
#pragma unroll
            for (int nt = 0; nt < 4; nt++) {
                uint2 b = *(const uint2*)(w1p + nt * 64);
                mma_t(R1 + 4 * nt, c0, c1, c2, c3, b.x, b.y);
            }
            // plane frags for w3 (same loads, cvt only)
            u32 p0 = tf32(p0f), p1 = tf32(p1f), p2 = tf32(p2f), p3 = tf32(p3f);
            u32 q0 = tf32(q0f), q1 = tf32(q1f), q2 = tf32(q2f), q3 = tf32(q3f);
            u32 s0 = tf32(s0f), s1 = tf32(s1f), s2 = tf32(s2f), s3 = tf32(s3f);
            const float* w3p = smem + FB_W3 + k8 * 4 * 64 + 2 * lane;
#pragma unroll
            for (int nt = 0; nt < 4; nt++) {
                uint2 b = *(const uint2*)(w3p + nt * 64);
                mma_t(Q + 4 * nt,      p0, p1, p2, p3, b.x, b.y);
                mma_t(Q + 16 + 4 * nt, q0, q1, q2, q3, b.x, b.y);
                mma_t(Q + 32 + 4 * nt, s0, s1, s2, s3, b.x, b.y);
            }
        }
        __syncwarp();   // all s0/s1 reads done -> overlay m0/m1k

        // ---- m0 build -> A0 (float2 stores) ----
#pragma unroll
        for (int nt = 0; nt < 4; nt++) {
            int u = nt * 8 + 2 * m4;
            *(float2*)&A0[r4 * TSTR + u] =
                make_float2(y0A * R0[4 * nt] * wt[4 * nt], y0A * R0[4 * nt + 1] * wt[4 * nt + 1]);
            *(float2*)&A0[(r4 + 8) * TSTR + u] =
                make_float2(y0B * R0[4 * nt + 2] * wt[4 * nt + 2], y0B * R0[4 * nt + 3] * wt[4 * nt + 3]);
            int wi = 4 * (nt + 4);
            *(float2*)&A0[r4 * TSTR + 32 + u] =
                make_float2(R1[4 * nt] * wt[wi], R1[4 * nt + 1] * wt[wi + 1]);
            *(float2*)&A0[(r4 + 8) * TSTR + 32 + u] =
                make_float2(R1[4 * nt + 2] * wt[wi + 2], R1[4 * nt + 3] * wt[wi + 3]);
        }

        // ---- m1k build -> A1..A3 (float2 stores) ----
#pragma unroll
        for (int k = 0; k < 3; k++) {
            float* Tk = (k == 0) ? A1 : ((k == 1) ? A2 : A3);
            float ykA = (k == 0) ? yA1 : ((k == 1) ? yA2 : yA3);
            float ykB = (k == 0) ? yB1 : ((k == 1) ? yB2 : yB3);
#pragma unroll
            for (int nt = 0; nt < 4; nt++) {
                int wi = 4 * (nt + 8), wj = 4 * (nt + 12);
                int u = nt * 8 + 2 * m4;
                *(float2*)&Tk[r4 * TSTR + u] =
                    make_float2(ykA * Pp[4 * nt] * wt[wi], ykA * Pp[4 * nt + 1] * wt[wi + 1]);
                *(float2*)&Tk[(r4 + 8) * TSTR + u] =
                    make_float2(ykB * Pp[4 * nt + 2] * wt[wi + 2], ykB * Pp[4 * nt + 3] * wt[wi + 3]);
                *(float2*)&Tk[r4 * TSTR + 32 + u] =
                    make_float2(y0A * Q[16 * k + 4 * nt] * wt[wj], y0A * Q[16 * k + 4 * nt + 1] * wt[wj + 1]);
                *(float2*)&Tk[(r4 + 8) * TSTR + 32 + u] =
                    make_float2(y0B * Q[16 * k + 4 * nt + 2] * wt[wj + 2], y0B * Q[16 * k + 4 * nt + 3] * wt[wj + 3]);
            }
        }
        __syncwarp();

        // ---- G8: O0 = m0@WA ; G9: Ok = m1k@WB (B shared) ----
        float O0[16];
#pragma unroll
        for (int i = 0; i < 16; i++) O0[i] = 0.f;
        gemm16s<4>(O0, A0, smem + FB_WA, r4, m4, lane);

        float O[48];
#pragma unroll
        for (int i = 0; i < 48; i++) O[i] = 0.f;
#pragma unroll
        for (int k8 = 0; k8 < 8; k8++) {
            u32 A[3][4];
#pragma unroll
            for (int k = 0; k < 3; k++) {
                const float* Tk = (k == 0) ? A1 : ((k == 1) ? A2 : A3);
                int o = r4 * TSTR + k8 * 8 + m4;
                A[k][0] = tf32(Tk[o]);
                A[k][1] = tf32(Tk[o + 8 * TSTR]);
                A[k][2] = tf32(Tk[o + 4]);
                A[k][3] = tf32(Tk[o + 8 * TSTR + 4]);
            }
            const float* wbp = smem + FB_WB + k8 * 4 * 64 + 2 * lane;
#pragma unroll
            for (int nt = 0; nt < 4; nt++) {
                uint2 b = *(const uint2*)(wbp + nt * 64);
#pragma unroll
                for (int k = 0; k < 3; k++)
                    mma_t(O + 16 * k + 4 * nt, A[k][0], A[k][1], A[k][2], A[k][3], b.x, b.y);
            }
        }
        __syncwarp();   // m reads done -> overlay out staging on A0/A1

        // ---- stage outputs (OB = A0, stride OSTR) ----
        float* OB = A0;
#pragma unroll
        for (int nt = 0; nt < 4; nt++) {
            int u = nt * 8 + 2 * m4;
            *(float2*)&OB[r4 * OSTR + u]       = make_float2(O0[4 * nt],     O0[4 * nt + 1]);
            *(float2*)&OB[(r4 + 8) * OSTR + u] = make_float2(O0[4 * nt + 2], O0[4 * nt + 3]);
#pragma unroll
            for (int k = 0; k < 3; k++) {
                int c = 32 + 3 * u + k;
                OB[r4 * OSTR + c]           = O[16 * k + 4 * nt];
                OB[r4 * OSTR + c + 3]       = O[16 * k + 4 * nt + 1];
                OB[(r4 + 8) * OSTR + c]     = O[16 * k + 4 * nt + 2];
                OB[(r4 + 8) * OSTR + c + 3] = O[16 * k + 4 * nt + 3];
            }
        }
        __syncwarp();
#pragma unroll
        for (int rr = 0; rr < 16; rr++)
            ((float4*)out)[(base + rr) * 32 + lane] = *(const float4*)&OB[rr * OSTR + 4 * lane];
        __syncwarp();
    }
}

// ---------------- launch ----------------
extern "C" void kernel_launch(void* const* d_in, const int* in_sizes, int n_in,
                              void* d_out, int out_size) {
    const float* x1a     = (const float*)d_in[0];
    const float* x1b     = (const float*)d_in[1];
    const float* x2      = (const float*)d_in[2];
    const float* scalars = (const float*)d_in[3];
    const float* w0      = (const float*)d_in[4];
    const float* w1      = (const float*)d_in[5];
    const float* w2      = (const float*)d_in[6];
    const float* w3      = (const float*)d_in[7];
    const float* Wl0     = (const float*)d_in[8];
    const float* Wl1     = (const float*)d_in[9];
    const float* Wm1     = (const float*)d_in[10];
    const float* Wm2     = (const float*)d_in[11];
    const float* Wm3     = (const float*)d_in[12];
    const float* Wf0     = (const float*)d_in[13];
    const float* Wf1     = (const float*)d_in[14];
    int n = in_sizes[0] / 128;

    cudaFuncSetAttribute(tp_mma_kernel, cudaFuncAttributeMaxDynamicSharedMemorySize, SMEM_BYTES);

    prep_kernel<<<112, 256>>>(w0, w1, w2, w3, Wl0, Wl1, Wm1, Wm2, Wm3, Wf0, Wf1);
    tp_mma_kernel<<<148, 32 * NWARP, SMEM_BYTES>>>(x1a, x1b, (const float4*)x2, scalars,
                                                   (float*)d_out, n);
}

// round 15
// speedup vs baseline: 1.1866x; 1.1094x over previous
#include <cuda_runtime.h>
#include <math.h>

typedef unsigned int u32;

// weight buffer (floats): six small matrices -> smem; Wm1/Wm2/Wm3 stay in GLOBAL (L2-hot)
#define FB_W0  0
#define FB_W1  2048
#define FB_W2  4096
#define FB_W3  6144
#define FB_WA  8192
#define FB_WB  10240
#define FB_SM  12288               // floats copied to smem
#define FB_WM1 12288
#define FB_WM2 16384
#define FB_WM3 20480
#define FB_TOT 28672

#define NWARP  10
#define TSTR   68
#define TFL    (16 * TSTR)          // 1088
#define OSTR   132
#define ARENA  (4 * TFL)            // 4352 floats
#define SMEM_FLOATS (FB_SM + NWARP * ARENA)    // 55808
#define SMEM_BYTES  (SMEM_FLOATS * 4)          // 223232

__device__ float g_cst;
__device__ float g_wbuf[FB_TOT];

__device__ __forceinline__ u32 tf32(float f) {
    u32 u; asm("cvt.rna.tf32.f32 %0,%1;" : "=r"(u) : "f"(f)); return u;
}
__device__ __forceinline__ void mma_t(float* d, u32 a0, u32 a1, u32 a2, u32 a3,
                                      u32 b0, u32 b1) {
    asm("mma.sync.aligned.m16n8k8.row.col.f32.tf32.tf32.f32 "
        "{%0,%1,%2,%3},{%4,%5,%6,%7},{%8,%9},{%0,%1,%2,%3};"
        : "+f"(d[0]), "+f"(d[1]), "+f"(d[2]), "+f"(d[3])
        : "r"(a0), "r"(a1), "r"(a2), "r"(a3), "r"(b0), "r"(b1));
}

// acc[4*NT] += T[16x64] @ W(smem) ; single-tf32 A and W
template<int NT>
__device__ __forceinline__ void gemm16s(float* acc, const float* T, const float* W,
                                        int r4, int m4, int lane) {
#pragma unroll
    for (int k8 = 0; k8 < 8; k8++) {
        const float* ap = T + r4 * TSTR + k8 * 8 + m4;
        u32 a0 = tf32(ap[0]);
        u32 a1 = tf32(ap[8 * TSTR]);
        u32 a2 = tf32(ap[4]);
        u32 a3 = tf32(ap[8 * TSTR + 4]);
        const float* wp = W + k8 * NT * 64 + 2 * lane;
#pragma unroll
        for (int nt = 0; nt < NT; nt++) {
            uint2 b = *(const uint2*)(wp + nt * 64);
            mma_t(acc + 4 * nt, a0, a1, a2, a3, b.x, b.y);
        }
    }
}

// same but W read from GLOBAL via __ldg (Wm1/Wm2/Wm3, L2-hot)
template<int NT>
__device__ __forceinline__ void gemm16g(float* acc, const float* T, const float* W,
                                        int r4, int m4, int lane) {
#pragma unroll
    for (int k8 = 0; k8 < 8; k8++) {
        const float* ap = T + r4 * TSTR + k8 * 8 + m4;
        u32 a0 = tf32(ap[0]);
        u32 a1 = tf32(ap[8 * TSTR]);
        u32 a2 = tf32(ap[4]);
        u32 a3 = tf32(ap[8 * TSTR + 4]);
        const float* wp = W + k8 * NT * 64 + 2 * lane;
#pragma unroll
        for (int nt = 0; nt < NT; nt++) {
            uint2 b = __ldg((const uint2*)(wp + nt * 64));
            mma_t(acc + 4 * nt, a0, a1, a2, a3, b.x, b.y);
        }
    }
}

// ---------------- prep ----------------
__global__ void prep_kernel(const float* __restrict__ w0, const float* __restrict__ w1,
                            const float* __restrict__ w2, const float* __restrict__ w3,
                            const float* __restrict__ Wl0, const float* __restrict__ Wl1,
                            const float* __restrict__ Wm1, const float* __restrict__ Wm2,
                            const float* __restrict__ Wm3,
                            const float* __restrict__ Wf0, const float* __restrict__ Wf1) {
    if (blockIdx.x == 0) {
        const int   N = 20000;
        const float h = 24.0f / 20000.0f;
        float local = 0.0f;
        for (int i = threadIdx.x; i <= N; i += blockDim.x) {
            float z   = -12.0f + h * (float)i;
            float s   = z / (1.0f + __expf(-z));
            float phi = __expf(-0.5f * z * z) * 0.3989422804014327f;
            float f   = s * s * phi;
            if (i == 0 || i == N) f *= 0.5f;
            local += f;
        }
        __shared__ float red[256];
        red[threadIdx.x] = local;
        __syncthreads();
        for (int s = 128; s > 0; s >>= 1) {
            if (threadIdx.x < s) red[threadIdx.x] += red[threadIdx.x + s];
            __syncthreads();
        }
        if (threadIdx.x == 0) g_cst = rsqrtf(red[0] * h);
    }

    int tid = blockIdx.x * blockDim.x + threadIdx.x;
    if (tid >= FB_TOT) return;
    const float INV_S3 = 0.57735026918962576f;
    const float WSCALE = 0.125f * 0.125f * 0.17677669529663687f;

    int mbase, N;
    if (tid < FB_SM)           { mbase = (tid / 2048) * 2048; N = 32; }
    else if (tid < FB_WM2)     { mbase = FB_WM1; N = 64; }
    else if (tid < FB_WM3)     { mbase = FB_WM2; N = 64; }
    else                       { mbase = FB_WM3; N = 128; }
    int idx = tid - mbase;
    int g = idx >> 6, pos = idx & 63, l = pos >> 1, hh = pos & 1;
    int ntn = N >> 3, k8 = g / ntn, n8 = g % ntn;
    int row = k8 * 8 + (l & 3) + 4 * hh;   // K index
    int col = n8 * 8 + (l >> 2);           // N index

    float v;
    if (tid < 2048)            v = w0[row * 32 + col];
    else if (tid < 4096)       v = w1[row * 32 + col] * INV_S3;
    else if (tid < 6144)       v = w2[row * 32 + col];
    else if (tid < 8192)       v = w3[row * 32 + col];
    else if (tid < FB_SM) {
        const float* L = (tid < 10240) ? Wl0 : Wl1;
        const float* F = (tid < 10240) ? Wf0 : Wf1;
        float acc = 0.0f;
        for (int w = 0; w < 32; w++) acc = fmaf(L[row * 32 + w], F[w * 32 + col], acc);
        v = acc * WSCALE;
    }
    else if (tid < FB_WM2)     v = Wm1[row * 64 + col] * 0.125f;
    else if (tid < FB_WM3)     v = Wm2[row * 64 + col] * 0.125f;
    else                       v = Wm3[row * 128 + col] * 0.125f;
    g_wbuf[tid] = __uint_as_float(tf32(v));
}

// ---------------- main ----------------
__global__ __launch_bounds__(32 * NWARP, 1)
void tp_mma_kernel(const float* __restrict__ x1a, const float* __restrict__ x1b,
                   const float4* __restrict__ x2, const float* __restrict__ scalars,
                   float* __restrict__ out, int nrows) {
    extern __shared__ float smem[];
    {
        const float4* src = (const float4*)g_wbuf;
        float4* dst = (float4*)smem;
        for (int i = threadIdx.x; i < FB_SM / 4; i += 32 * NWARP) dst[i] = src[i];
    }
    __syncthreads();
    const float cst = g_cst;
    const float* wm1g = g_wbuf + FB_WM1;
    const float* wm2g = g_wbuf + FB_WM2;
    const float* wm3g = g_wbuf + FB_WM3;

    const int lane = threadIdx.x & 31, wid = threadIdx.x >> 5;
    const int r4 = lane >> 2, m4 = lane & 3;

    float* A0 = smem + FB_SM + wid * ARENA;
    float* A1 = A0 + TFL;
    float* A2 = A1 + TFL;
    float* A3 = A2 + TFL;

    const int gw = blockIdx.x * NWARP + wid, gwn = gridDim.x * NWARP;
    const int ntiles = nrows >> 4;

    for (int t = gw; t < ntiles; t += gwn) {
        const int base = t * 16;

        // ---- stage scalars (A0) AND x1-tail planes (A1..A3) + y: issue all global
        //      loads up front so their latency overlaps the whole MLP phase ----
#pragma unroll
        for (int j = 0; j < 8; j++) {
            int row = r4 + 8 * (j & 1), f4 = m4 + 4 * (j >> 1);
            *(float4*)&A0[row * TSTR + 4 * f4] =
                ((const float4*)scalars)[(base + row) * 16 + f4];
        }
#pragma unroll
        for (int it = 0; it < 8; it++) {
            int sid = it * 32 + lane;
            int row = sid >> 4, within = sid & 15;
            int arr = within >> 3, q = within & 7;
            const float4* src = arr ? (const float4*)x1b : (const float4*)x1a;
            int p = (base + row) * 32 + 8 + 3 * q;
            float4 v0 = src[p], v1 = src[p + 1], v2 = src[p + 2];
            int off = row * TSTR + arr * 32 + 4 * q;
            *(float4*)&A1[off] = make_float4(v0.x, v0.w, v1.z, v2.y);
            *(float4*)&A2[off] = make_float4(v0.y, v1.x, v1.w, v2.z);
            *(float4*)&A3[off] = make_float4(v0.z, v1.y, v2.x, v2.w);
        }
        float4 yA = __ldg(&x2[base + r4]);
        float4 yB = __ldg(&x2[base + r4 + 8]);
        const float y0A = yA.x, yA1 = yA.y, yA2 = yA.z, yA3 = yA.w;
        const float y0B = yB.x, yB1 = yB.y, yB2 = yB.z, yB3 = yB.w;
        __syncwarp();

        // ---- MLP GEMM1 -> silu -> GEMM2 -> silu -> GEMM3 (weights via L2) ----
        float h[32];
#pragma unroll
        for (int i = 0; i < 32; i++) h[i] = 0.f;
        gemm16g<8>(h, A0, wm1g, r4, m4, lane);
        __syncwarp();
#pragma unroll
        for (int nt = 0; nt < 8; nt++) {
            float a = h[4 * nt],     b = h[4 * nt + 1];
            float c = h[4 * nt + 2], d = h[4 * nt + 3];
            float2 lo = {cst * a / (1.f + __expf(-a)), cst * b / (1.f + __expf(-b))};
            float2 hi = {cst * c / (1.f + __expf(-c)), cst * d / (1.f + __expf(-d))};
            *(float2*)&A0[r4 * TSTR + nt * 8 + 2 * m4]       = lo;
            *(float2*)&A0[(r4 + 8) * TSTR + nt * 8 + 2 * m4] = hi;
        }
        __syncwarp();
#pragma unroll
        for (int i = 0; i < 32; i++) h[i] = 0.f;
        gemm16g<8>(h, A0, wm2g, r4, m4, lane);
        __syncwarp();
#pragma unroll
        for (int nt = 0; nt < 8; nt++) {
            float a = h[4 * nt],     b = h[4 * nt + 1];
            float c = h[4 * nt + 2], d = h[4 * nt + 3];
            float2 lo = {cst * a / (1.f + __expf(-a)), cst * b / (1.f + __expf(-b))};
            float2 hi = {cst * c / (1.f + __expf(-c)), cst * d / (1.f + __expf(-d))};
            *(float2*)&A0[r4 * TSTR + nt * 8 + 2 * m4]       = lo;
            *(float2*)&A0[(r4 + 8) * TSTR + nt * 8 + 2 * m4] = hi;
        }
        __syncwarp();
        float wt[64];
#pragma unroll
        for (int i = 0; i < 64; i++) wt[i] = 0.f;
        gemm16g<16>(wt, A0, wm3g, r4, m4, lane);
        __syncwarp();

        // ---- stage x1 head -> s0 (A0), float4 ----
#pragma unroll
        for (int it = 0; it < 8; it++) {
            int fid = it * 32 + lane;
            int row = fid >> 4, within = fid & 15;
            int arr = within >> 3, j = within & 7;
            const float4* src = arr ? (const float4*)x1b : (const float4*)x1a;
            float4 v = src[(base + row) * 32 + j];
            *(float4*)&A0[row * TSTR + arr * 32 + 4 * j] = v;
        }
        __syncwarp();

        // ---- G4/G5: R0 = s0@w0, Pp = s0@w2 (shared A frags) ----
        float R0[16], Pp[16], R1[16];
#pragma unroll
        for (int i = 0; i < 16; i++) { R0[i] = 0.f; Pp[i] = 0.f; R1[i] = 0.f; }
#pragma unroll
        for (int k8 = 0; k8 < 8; k8++) {
            const float* ap = A0 + r4 * TSTR + k8 * 8 + m4;
            u32 a0 = tf32(ap[0]);
            u32 a1 = tf32(ap[8 * TSTR]);
            u32 a2 = tf32(ap[4]);
            u32 a3 = tf32(ap[8 * TSTR + 4]);
            const float* w0p = smem + FB_W0 + k8 * 4 * 64 + 2 * lane;
            const float* w2p = smem + FB_W2 + k8 * 4 * 64 + 2 * lane;
#pragma unroll
            for (int nt = 0; nt < 4; nt++) {
                uint2 b0 = *(const uint2*)(w0p + nt * 64);
                mma_t(R0 + 4 * nt, a0, a1, a2, a3, b0.x, b0.y);
                uint2 b2 = *(const uint2*)(w2p + nt * 64);
                mma_t(Pp + 4 * nt, a0, a1, a2, a3, b2.x, b2.y);
            }
        }

        // ---- G6: R1 = t1@w1, t1 frags built on the fly ----
#pragma unroll
        for (int k8 = 0; k8 < 8; k8++) {
            int o = r4 * TSTR + k8 * 8 + m4;
            float t0  = A1[o] * yA1 + A2[o] * yA2 + A3[o] * yA3;
            float t2  = A1[o + 4] * yA1 + A2[o + 4] * yA2 + A3[o + 4] * yA3;
            float t1v = A1[o + 8 * TSTR] * yB1 + A2[o + 8 * TSTR] * yB2 + A3[o + 8 * TSTR] * yB3;
            float t3  = A1[o + 8 * TSTR + 4] * yB1 + A2[o + 8 * TSTR + 4] * yB2 + A3[o + 8 * TSTR + 4] * yB3;
            u32 a0 = tf32(t0), a1 = tf32(t1v), a2 = tf32(t2), a3 = tf32(t3);
            const float* w1p = smem + FB_W1 + k8 * 4 * 64 + 2 * lane;
#pragma unroll
            for (int nt = 0; nt < 4; nt++) {
                uint2 b = *(const uint2*)(w1p + nt * 64);
                mma_t(R1 + 4 * nt, a0, a1, a2, a3, b.x, b.y);
            }
        }
        __syncwarp();   // s0 reads done -> overlay m0 on A0

        // ---- m0 build -> A0 (float2 stores) ----
#pragma unroll
        for (int nt = 0; nt < 4; nt++) {
            int u = nt * 8 + 2 * m4;
            *(float2*)&A0[r4 * TSTR + u] =
                make_float2(y0A * R0[4 * nt] * wt[4 * nt], y0A * R0[4 * nt + 1] * wt[4 * nt + 1]);
            *(float2*)&A0[(r4 + 8) * TSTR + u] =
                make_float2(y0B * R0[4 * nt + 2] * wt[4 * nt + 2], y0B * R0[4 * nt + 3] * wt[4 * nt + 3]);
            int wi = 4 * (nt + 4);
            *(float2*)&A0[r4 * TSTR + 32 + u] =
                make_float2(R1[4 * nt] * wt[wi], R1[4 * nt + 1] * wt[wi + 1]);
            *(float2*)&A0[(r4 + 8) * TSTR + 32 + u] =
                make_float2(R1[4 * nt + 2] * wt[wi + 2], R1[4 * nt + 3] * wt[wi + 3]);
        }

        // ---- G7: Qk = s1k@w3 (B shared across k) ----
        float Q[48];
#pragma unroll
        for (int i = 0; i < 48; i++) Q[i] = 0.f;
#pragma unroll
        for (int k8 = 0; k8 < 8; k8++) {
            u32 A[3][4];
#pragma unroll
            for (int k = 0; k < 3; k++) {
                const float* Tk = (k == 0) ? A1 : ((k == 1) ? A2 : A3);
                int o = r4 * TSTR + k8 * 8 + m4;
                A[k][0] = tf32(Tk[o]);
                A[k][1] = tf32(Tk[o + 8 * TSTR]);
                A[k][2] = tf32(Tk[o + 4]);
                A[k][3] = tf32(Tk[o + 8 * TSTR + 4]);
            }
            const float* w3p = smem + FB_W3 + k8 * 4 * 64 + 2 * lane;
#pragma unroll
            for (int nt = 0; nt < 4; nt++) {
                uint2 b = *(const uint2*)(w3p + nt * 64);
#pragma unroll
                for (int k = 0; k < 3; k++)
                    mma_t(Q + 16 * k + 4 * nt, A[k][0], A[k][1], A[k][2], A[k][3], b.x, b.y);
            }
        }
        __syncwarp();   // s1 reads done -> overlay m1k

        // ---- m1k build -> A1..A3 (float2 stores) ----
#pragma unroll
        for (int k = 0; k < 3; k++) {
            float* Tk = (k == 0) ? A1 : ((k == 1) ? A2 : A3);
            float ykA = (k == 0) ? yA1 : ((k == 1) ? yA2 : yA3);
            float ykB = (k == 0) ? yB1 : ((k == 1) ? yB2 : yB3);
#pragma unroll
            for (int nt = 0; nt < 4; nt++) {
                int wi = 4 * (nt + 8), wj = 4 * (nt + 12);
                int u = nt * 8 + 2 * m4;
                *(float2*)&Tk[r4 * TSTR + u] =
                    make_float2(ykA * Pp[4 * nt] * wt[wi], ykA * Pp[4 * nt + 1] * wt[wi + 1]);
                *(float2*)&Tk[(r4 + 8) * TSTR + u] =
                    make_float2(ykB * Pp[4 * nt + 2] * wt[wi + 2], ykB * Pp[4 * nt + 3] * wt[wi + 3]);
                *(float2*)&Tk[r4 * TSTR + 32 + u] =
                    make_float2(y0A * Q[16 * k + 4 * nt] * wt[wj], y0A * Q[16 * k + 4 * nt + 1] * wt[wj + 1]);
                *(float2*)&Tk[(r4 + 8) * TSTR + 32 + u] =
                    make_float2(y0B * Q[16 * k + 4 * nt + 2] * wt[wj + 2], y0B * Q[16 * k + 4 * nt + 3] * wt[wj + 3]);
            }
        }
        __syncwarp();

        // ---- G8: O0 = m0@WA ; G9: Ok = m1k@WB (B shared) ----
        float O0[16];
#pragma unroll
        for (int i = 0; i < 16; i++) O0[i] = 0.f;
        gemm16s<4>(O0, A0, smem + FB_WA, r4, m4, lane);

        float O[48];
#pragma unroll
        for (int i = 0; i < 48; i++) O[i] = 0.f;
#pragma unroll
        for (int k8 = 0; k8 < 8; k8++) {
            u32 A[3][4];
#pragma unroll
            for (int k = 0; k < 3; k++) {
                const float* Tk = (k == 0) ? A1 : ((k == 1) ? A2 : A3);
                int o = r4 * TSTR + k8 * 8 + m4;
                A[k][0] = tf32(Tk[o]);
                A[k][1] = tf32(Tk[o + 8 * TSTR]);
                A[k][2] = tf32(Tk[o + 4]);
                A[k][3] = tf32(Tk[o + 8 * TSTR + 4]);
            }
            const float* wbp = smem + FB_WB + k8 * 4 * 64 + 2 * lane;
#pragma unroll
            for (int nt = 0; nt < 4; nt++) {
                uint2 b = *(const uint2*)(wbp + nt * 64);
#pragma unroll
                for (int k = 0; k < 3; k++)
                    mma_t(O + 16 * k + 4 * nt, A[k][0], A[k][1], A[k][2], A[k][3], b.x, b.y);
            }
        }
        __syncwarp();   // m reads done -> overlay out staging on A0/A1

        // ---- stage outputs (OB = A0, stride OSTR) ----
        float* OB = A0;
#pragma unroll
        for (int nt = 0; nt < 4; nt++) {
            int u = nt * 8 + 2 * m4;
            *(float2*)&OB[r4 * OSTR + u]       = make_float2(O0[4 * nt],     O0[4 * nt + 1]);
            *(float2*)&OB[(r4 + 8) * OSTR + u] = make_float2(O0[4 * nt + 2], O0[4 * nt + 3]);
#pragma unroll
            for (int k = 0; k < 3; k++) {
                int c = 32 + 3 * u + k;
                OB[r4 * OSTR + c]           = O[16 * k + 4 * nt];
                OB[r4 * OSTR + c + 3]       = O[16 * k + 4 * nt + 1];
                OB[(r4 + 8) * OSTR + c]     = O[16 * k + 4 * nt + 2];
                OB[(r4 + 8) * OSTR + c + 3] = O[16 * k + 4 * nt + 3];
            }
        }
        __syncwarp();
#pragma unroll
        for (int rr = 0; rr < 16; rr++)
            ((float4*)out)[(base + rr) * 32 + lane] = *(const float4*)&OB[rr * OSTR + 4 * lane];
        __syncwarp();
    }
}

// ---------------- launch ----------------
extern "C" void kernel_launch(void* const* d_in, const int* in_sizes, int n_in,
                              void* d_out, int out_size) {
    const float* x1a     = (const float*)d_in[0];
    const float* x1b     = (const float*)d_in[1];
    const float* x2      = (const float*)d_in[2];
    const float* scalars = (const float*)d_in[3];
    const float* w0      = (const float*)d_in[4];
    const float* w1      = (const float*)d_in[5];
    const float* w2      = (const float*)d_in[6];
    const float* w3      = (const float*)d_in[7];
    const float* Wl0     = (const float*)d_in[8];
    const float* Wl1     = (const float*)d_in[9];
    const float* Wm1     = (const float*)d_in[10];
    const float* Wm2     = (const float*)d_in[11];
    const float* Wm3     = (const float*)d_in[12];
    const float* Wf0     = (const float*)d_in[13];
    const float* Wf1     = (const float*)d_in[14];
    int n = in_sizes[0] / 128;

    cudaFuncSetAttribute(tp_mma_kernel, cudaFuncAttributeMaxDynamicSharedMemorySize, SMEM_BYTES);

    prep_kernel<<<112, 256>>>(w0, w1, w2, w3, Wl0, Wl1, Wm1, Wm2, Wm3, Wf0, Wf1);
    tp_mma_kernel<<<148, 32 * NWARP, SMEM_BYTES>>>(x1a, x1b, (const float4*)x2, scalars,
                                                   (float*)d_out, n);
}

// round 16
// speedup vs baseline: 1.2160x; 1.0248x over previous
#include <cuda_runtime.h>
#include <math.h>

typedef unsigned int u32;

// weight buffer (floats): six small matrices -> smem; Wm1/Wm2/Wm3 stay in GLOBAL (L2-hot)
#define FB_W0  0
#define FB_W1  2048
#define FB_W2  4096
#define FB_W3  6144
#define FB_WA  8192
#define FB_WB  10240
#define FB_SM  12288               // floats copied to smem
#define FB_WM1 12288
#define FB_WM2 16384
#define FB_WM3 20480
#define FB_TOT 28672

#define NWARP  10
#define TSTR   68
#define TFL    (16 * TSTR)          // 1088
#define OSTR   132
#define ARENA  (4 * TFL)            // 4352 floats
#define SMEM_FLOATS (FB_SM + NWARP * ARENA)    // 55808
#define SMEM_BYTES  (SMEM_FLOATS * 4)          // 223232

__device__ float g_cst;
__device__ float g_wbuf[FB_TOT];

__device__ __forceinline__ u32 tf32(float f) {
    u32 u; asm("cvt.rna.tf32.f32 %0,%1;" : "=r"(u) : "f"(f)); return u;
}
__device__ __forceinline__ void mma_t(float* d, u32 a0, u32 a1, u32 a2, u32 a3,
                                      u32 b0, u32 b1) {
    asm("mma.sync.aligned.m16n8k8.row.col.f32.tf32.tf32.f32 "
        "{%0,%1,%2,%3},{%4,%5,%6,%7},{%8,%9},{%0,%1,%2,%3};"
        : "+f"(d[0]), "+f"(d[1]), "+f"(d[2]), "+f"(d[3])
        : "r"(a0), "r"(a1), "r"(a2), "r"(a3), "r"(b0), "r"(b1));
}

// acc[4*NT] += T[16x64] @ W(smem) ; single-tf32 A and W
template<int NT>
__device__ __forceinline__ void gemm16s(float* acc, const float* T, const float* W,
                                        int r4, int m4, int lane) {
#pragma unroll
    for (int k8 = 0; k8 < 8; k8++) {
        const float* ap = T + r4 * TSTR + k8 * 8 + m4;
        u32 a0 = tf32(ap[0]);
        u32 a1 = tf32(ap[8 * TSTR]);
        u32 a2 = tf32(ap[4]);
        u32 a3 = tf32(ap[8 * TSTR + 4]);
        const float* wp = W + k8 * NT * 64 + 2 * lane;
#pragma unroll
        for (int nt = 0; nt < NT; nt++) {
            uint2 b = *(const uint2*)(wp + nt * 64);
            mma_t(acc + 4 * nt, a0, a1, a2, a3, b.x, b.y);
        }
    }
}

// same but W read from GLOBAL via __ldg (Wm1/Wm2/Wm3, L2-hot)
template<int NT>
__device__ __forceinline__ void gemm16g(float* acc, const float* T, const float* W,
                                        int r4, int m4, int lane) {
#pragma unroll
    for (int k8 = 0; k8 < 8; k8++) {
        const float* ap = T + r4 * TSTR + k8 * 8 + m4;
        u32 a0 = tf32(ap[0]);
        u32 a1 = tf32(ap[8 * TSTR]);
        u32 a2 = tf32(ap[4]);
        u32 a3 = tf32(ap[8 * TSTR + 4]);
        const float* wp = W + k8 * NT * 64 + 2 * lane;
#pragma unroll
        for (int nt = 0; nt < NT; nt++) {
            uint2 b = __ldg((const uint2*)(wp + nt * 64));
            mma_t(acc + 4 * nt, a0, a1, a2, a3, b.x, b.y);
        }
    }
}

// ---------------- prep ----------------
__global__ void prep_kernel(const float* __restrict__ w0, const float* __restrict__ w1,
                            const float* __restrict__ w2, const float* __restrict__ w3,
                            const float* __restrict__ Wl0, const float* __restrict__ Wl1,
                            const float* __restrict__ Wm1, const float* __restrict__ Wm2,
                            const float* __restrict__ Wm3,
                            const float* __restrict__ Wf0, const float* __restrict__ Wf1) {
    if (blockIdx.x == 0) {
        const int   N = 20000;
        const float h = 24.0f / 20000.0f;
        float local = 0.0f;
        for (int i = threadIdx.x; i <= N; i += blockDim.x) {
            float z   = -12.0f + h * (float)i;
            float s   = z / (1.0f + __expf(-z));
            float phi = __expf(-0.5f * z * z) * 0.3989422804014327f;
            float f   = s * s * phi;
            if (i == 0 || i == N) f *= 0.5f;
            local += f;
        }
        __shared__ float red[256];
        red[threadIdx.x] = local;
        __syncthreads();
        for (int s = 128; s > 0; s >>= 1) {
            if (threadIdx.x < s) red[threadIdx.x] += red[threadIdx.x + s];
            __syncthreads();
        }
        if (threadIdx.x == 0) g_cst = rsqrtf(red[0] * h);
    }

    int tid = blockIdx.x * blockDim.x + threadIdx.x;
    if (tid >= FB_TOT) return;
    const float INV_S3 = 0.57735026918962576f;
    const float WSCALE = 0.125f * 0.125f * 0.17677669529663687f;

    int mbase, N;
    if (tid < FB_SM)           { mbase = (tid / 2048) * 2048; N = 32; }
    else if (tid < FB_WM2)     { mbase = FB_WM1; N = 64; }
    else if (tid < FB_WM3)     { mbase = FB_WM2; N = 64; }
    else                       { mbase = FB_WM3; N = 128; }
    int idx = tid - mbase;
    int g = idx >> 6, pos = idx & 63, l = pos >> 1, hh = pos & 1;
    int ntn = N >> 3, k8 = g / ntn, n8 = g % ntn;
    int row = k8 * 8 + (l & 3) + 4 * hh;   // K index
    int col = n8 * 8 + (l >> 2);           // N index

    float v;
    if (tid < 2048)            v = w0[row * 32 + col];
    else if (tid < 4096)       v = w1[row * 32 + col] * INV_S3;
    else if (tid < 6144)       v = w2[row * 32 + col];
    else if (tid < 8192)       v = w3[row * 32 + col];
    else if (tid < FB_SM) {
        const float* L = (tid < 10240) ? Wl0 : Wl1;
        const float* F = (tid < 10240) ? Wf0 : Wf1;
        float acc = 0.0f;
        for (int w = 0; w < 32; w++) acc = fmaf(L[row * 32 + w], F[w * 32 + col], acc);
        v = acc * WSCALE;
    }
    else if (tid < FB_WM2)     v = Wm1[row * 64 + col] * 0.125f;
    else if (tid < FB_WM3)     v = Wm2[row * 64 + col] * 0.125f;
    else                       v = Wm3[row * 128 + col] * 0.125f;
    g_wbuf[tid] = __uint_as_float(tf32(v));
}

// ---------------- main ----------------
__global__ __launch_bounds__(32 * NWARP, 1)
void tp_mma_kernel(const float* __restrict__ x1a, const float* __restrict__ x1b,
                   const float4* __restrict__ x2, const float* __restrict__ scalars,
                   float* __restrict__ out, int nrows) {
    extern __shared__ float smem[];
    {
        const float4* src = (const float4*)g_wbuf;
        float4* dst = (float4*)smem;
        for (int i = threadIdx.x; i < FB_SM / 4; i += 32 * NWARP) dst[i] = src[i];
    }
    __syncthreads();
    const float cst = g_cst;
    const float* wm1g = g_wbuf + FB_WM1;
    const float* wm2g = g_wbuf + FB_WM2;
    const float* wm3g = g_wbuf + FB_WM3;

    const int lane = threadIdx.x & 31, wid = threadIdx.x >> 5;
    const int r4 = lane >> 2, m4 = lane & 3;

    float* A0 = smem + FB_SM + wid * ARENA;
    float* A1 = A0 + TFL;
    float* A2 = A1 + TFL;
    float* A3 = A2 + TFL;

    const int gw = blockIdx.x * NWARP + wid, gwn = gridDim.x * NWARP;
    const int ntiles = nrows >> 4;

    // s0-head prefetch lane mapping (fixed per thread)
    const int h_fid = lane;                 // iterated with +32
    for (int t = gw; t < ntiles; t += gwn) {
        const int base = t * 16;

        // ---- tile start: issue ALL global loads (scalars, x1 tail, x1 head, y) ----
#pragma unroll
        for (int j = 0; j < 8; j++) {
            int row = r4 + 8 * (j & 1), f4 = m4 + 4 * (j >> 1);
            *(float4*)&A0[row * TSTR + 4 * f4] =
                ((const float4*)scalars)[(base + row) * 16 + f4];
        }
#pragma unroll
        for (int it = 0; it < 8; it++) {
            int sid = it * 32 + lane;
            int row = sid >> 4, within = sid & 15;
            int arr = within >> 3, q = within & 7;
            const float4* src = arr ? (const float4*)x1b : (const float4*)x1a;
            int p = (base + row) * 32 + 8 + 3 * q;
            float4 v0 = src[p], v1 = src[p + 1], v2 = src[p + 2];
            int off = row * TSTR + arr * 32 + 4 * q;
            *(float4*)&A1[off] = make_float4(v0.x, v0.w, v1.z, v2.y);
            *(float4*)&A2[off] = make_float4(v0.y, v1.x, v1.w, v2.z);
            *(float4*)&A3[off] = make_float4(v0.z, v1.y, v2.x, v2.w);
        }
        // s0 head -> REGISTERS (latency overlaps the whole MLP phase)
        float4 hv[8];
#pragma unroll
        for (int it = 0; it < 8; it++) {
            int fid = it * 32 + h_fid;
            int row = fid >> 4, within = fid & 15;
            int arr = within >> 3, j = within & 7;
            const float4* src = arr ? (const float4*)x1b : (const float4*)x1a;
            hv[it] = __ldg(&src[(base + row) * 32 + j]);
        }
        float4 yA = __ldg(&x2[base + r4]);
        float4 yB = __ldg(&x2[base + r4 + 8]);
        const float y0A = yA.x, yA1 = yA.y, yA2 = yA.z, yA3 = yA.w;
        const float y0B = yB.x, yB1 = yB.y, yB2 = yB.z, yB3 = yB.w;
        __syncwarp();

        // ---- MLP GEMM1 -> silu -> GEMM2 -> silu -> GEMM3 (weights via L2) ----
        float h[32];
#pragma unroll
        for (int i = 0; i < 32; i++) h[i] = 0.f;
        gemm16g<8>(h, A0, wm1g, r4, m4, lane);
        __syncwarp();
#pragma unroll
        for (int nt = 0; nt < 8; nt++) {
            float a = h[4 * nt],     b = h[4 * nt + 1];
            float c = h[4 * nt + 2], d = h[4 * nt + 3];
            float2 lo = {cst * a / (1.f + __expf(-a)), cst * b / (1.f + __expf(-b))};
            float2 hi = {cst * c / (1.f + __expf(-c)), cst * d / (1.f + __expf(-d))};
            *(float2*)&A0[r4 * TSTR + nt * 8 + 2 * m4]       = lo;
            *(float2*)&A0[(r4 + 8) * TSTR + nt * 8 + 2 * m4] = hi;
        }
        __syncwarp();
#pragma unroll
        for (int i = 0; i < 32; i++) h[i] = 0.f;
        gemm16g<8>(h, A0, wm2g, r4, m4, lane);
        __syncwarp();
#pragma unroll
        for (int nt = 0; nt < 8; nt++) {
            float a = h[4 * nt],     b = h[4 * nt + 1];
            float c = h[4 * nt + 2], d = h[4 * nt + 3];
            float2 lo = {cst * a / (1.f + __expf(-a)), cst * b / (1.f + __expf(-b))};
            float2 hi = {cst * c / (1.f + __expf(-c)), cst * d / (1.f + __expf(-d))};
            *(float2*)&A0[r4 * TSTR + nt * 8 + 2 * m4]       = lo;
            *(float2*)&A0[(r4 + 8) * TSTR + nt * 8 + 2 * m4] = hi;
        }
        __syncwarp();
        float wt[64];
#pragma unroll
        for (int i = 0; i < 64; i++) wt[i] = 0.f;
        gemm16g<16>(wt, A0, wm3g, r4, m4, lane);
        __syncwarp();

        // ---- s0 head: registers -> A0 (STS only; LDG already done) ----
#pragma unroll
        for (int it = 0; it < 8; it++) {
            int fid = it * 32 + h_fid;
            int row = fid >> 4, within = fid & 15;
            int arr = within >> 3, j = within & 7;
            *(float4*)&A0[row * TSTR + arr * 32 + 4 * j] = hv[it];
        }
        __syncwarp();

        // ---- G4/G5: R0 = s0@w0, Pp = s0@w2 (shared A frags) ----
        float R0[16], Pp[16], R1[16];
#pragma unroll
        for (int i = 0; i < 16; i++) { R0[i] = 0.f; Pp[i] = 0.f; R1[i] = 0.f; }
#pragma unroll
        for (int k8 = 0; k8 < 8; k8++) {
            const float* ap = A0 + r4 * TSTR + k8 * 8 + m4;
            u32 a0 = tf32(ap[0]);
            u32 a1 = tf32(ap[8 * TSTR]);
            u32 a2 = tf32(ap[4]);
            u32 a3 = tf32(ap[8 * TSTR + 4]);
            const float* w0p = smem + FB_W0 + k8 * 4 * 64 + 2 * lane;
            const float* w2p = smem + FB_W2 + k8 * 4 * 64 + 2 * lane;
#pragma unroll
            for (int nt = 0; nt < 4; nt++) {
                uint2 b0 = *(const uint2*)(w0p + nt * 64);
                mma_t(R0 + 4 * nt, a0, a1, a2, a3, b0.x, b0.y);
                uint2 b2 = *(const uint2*)(w2p + nt * 64);
                mma_t(Pp + 4 * nt, a0, a1, a2, a3, b2.x, b2.y);
            }
        }

        // ---- G6: R1 = t1@w1, t1 frags built on the fly ----
#pragma unroll
        for (int k8 = 0; k8 < 8; k8++) {
            int o = r4 * TSTR + k8 * 8 + m4;
            float t0  = A1[o] * yA1 + A2[o] * yA2 + A3[o] * yA3;
            float t2  = A1[o + 4] * yA1 + A2[o + 4] * yA2 + A3[o + 4] * yA3;
            float t1v = A1[o + 8 * TSTR] * yB1 + A2[o + 8 * TSTR] * yB2 + A3[o + 8 * TSTR] * yB3;
            float t3  = A1[o + 8 * TSTR + 4] * yB1 + A2[o + 8 * TSTR + 4] * yB2 + A3[o + 8 * TSTR + 4] * yB3;
            u32 a0 = tf32(t0), a1 = tf32(t1v), a2 = tf32(t2), a3 = tf32(t3);
            const float* w1p = smem + FB_W1 + k8 * 4 * 64 + 2 * lane;
#pragma unroll
            for (int nt = 0; nt < 4; nt++) {
                uint2 b = *(const uint2*)(w1p + nt * 64);
                mma_t(R1 + 4 * nt, a0, a1, a2, a3, b.x, b.y);
            }
        }
        __syncwarp();   // s0 reads done -> overlay m0 on A0

        // ---- m0 build -> A0 (float2 stores) ----
#pragma unroll
        for (int nt = 0; nt < 4; nt++) {
            int u = nt * 8 + 2 * m4;
            *(float2*)&A0[r4 * TSTR + u] =
                make_float2(y0A * R0[4 * nt] * wt[4 * nt], y0A * R0[4 * nt + 1] * wt[4 * nt + 1]);
            *(float2*)&A0[(r4 + 8) * TSTR + u] =
                make_float2(y0B * R0[4 * nt + 2] * wt[4 * nt + 2], y0B * R0[4 * nt + 3] * wt[4 * nt + 3]);
            int wi = 4 * (nt + 4);
            *(float2*)&A0[r4 * TSTR + 32 + u] =
                make_float2(R1[4 * nt] * wt[wi], R1[4 * nt + 1] * wt[wi + 1]);
            *(float2*)&A0[(r4 + 8) * TSTR + 32 + u] =
                make_float2(R1[4 * nt + 2] * wt[wi + 2], R1[4 * nt + 3] * wt[wi + 3]);
        }

        // ---- G7: Qk = s1k@w3 (B shared across k) ----
        float Q[48];
#pragma unroll
        for (int i = 0; i < 48; i++) Q[i] = 0.f;
#pragma unroll
        for (int k8 = 0; k8 < 8; k8++) {
            u32 A[3][4];
#pragma unroll
            for (int k = 0; k < 3; k++) {
                const float* Tk = (k == 0) ? A1 : ((k == 1) ? A2 : A3);
                int o = r4 * TSTR + k8 * 8 + m4;
                A[k][0] = tf32(Tk[o]);
                A[k][1] = tf32(Tk[o + 8 * TSTR]);
                A[k][2] = tf32(Tk[o + 4]);
                A[k][3] = tf32(Tk[o + 8 * TSTR + 4]);
            }
            const float* w3p = smem + FB_W3 + k8 * 4 * 64 + 2 * lane;
#pragma unroll
            for (int nt = 0; nt < 4; nt++) {
                uint2 b = *(const uint2*)(w3p + nt * 64);
#pragma unroll
                for (int k = 0; k < 3; k++)
                    mma_t(Q + 16 * k + 4 * nt, A[k][0], A[k][1], A[k][2], A[k][3], b.x, b.y);
            }
        }
        __syncwarp();   // s1 reads done -> overlay m1k

        // ---- m1k build -> A1..A3 (float2 stores) ----
#pragma unroll
        for (int k = 0; k < 3; k++) {
            float* Tk = (k == 0) ? A1 : ((k == 1) ? A2 : A3);
            float ykA = (k == 0) ? yA1 : ((k == 1) ? yA2 : yA3);
            float ykB = (k == 0) ? yB1 : ((k == 1) ? yB2 : yB3);
#pragma unroll
            for (int nt = 0; nt < 4; nt++) {
                int wi = 4 * (nt + 8), wj = 4 * (nt + 12);
                int u = nt * 8 + 2 * m4;
                *(float2*)&Tk[r4 * TSTR + u] =
                    make_float2(ykA * Pp[4 * nt] * wt[wi], ykA * Pp[4 * nt + 1] * wt[wi + 1]);
                *(float2*)&Tk[(r4 + 8) * TSTR + u] =
                    make_float2(ykB * Pp[4 * nt + 2] * wt[wi + 2], ykB * Pp[4 * nt + 3] * wt[wi + 3]);
                *(float2*)&Tk[r4 * TSTR + 32 + u] =
                    make_float2(y0A * Q[16 * k + 4 * nt] * wt[wj], y0A * Q[16 * k + 4 * nt + 1] * wt[wj + 1]);
                *(float2*)&Tk[(r4 + 8) * TSTR + 32 + u] =
                    make_float2(y0B * Q[16 * k + 4 * nt + 2] * wt[wj + 2], y0B * Q[16 * k + 4 * nt + 3] * wt[wj + 3]);
            }
        }
        __syncwarp();

        // ---- G8: O0 = m0@WA ; G9: Ok = m1k@WB (B shared) ----
        float O0[16];
#pragma unroll
        for (int i = 0; i < 16; i++) O0[i] = 0.f;
        gemm16s<4>(O0, A0, smem + FB_WA, r4, m4, lane);

        float O[48];
#pragma unroll
        for (int i = 0; i < 48; i++) O[i] = 0.f;
#pragma unroll
        for (int k8 = 0; k8 < 8; k8++) {
            u32 A[3][4];
#pragma unroll
            for (int k = 0; k < 3; k++) {
                const float* Tk = (k == 0) ? A1 : ((k == 1) ? A2 : A3);
                int o = r4 * TSTR + k8 * 8 + m4;
                A[k][0] = tf32(Tk[o]);
                A[k][1] = tf32(Tk[o + 8 * TSTR]);
                A[k][2] = tf32(Tk[o + 4]);
                A[k][3] = tf32(Tk[o + 8 * TSTR + 4]);
            }
            const float* wbp = smem + FB_WB + k8 * 4 * 64 + 2 * lane;
#pragma unroll
            for (int nt = 0; nt < 4; nt++) {
                uint2 b = *(const uint2*)(wbp + nt * 64);
#pragma unroll
                for (int k = 0; k < 3; k++)
                    mma_t(O + 16 * k + 4 * nt, A[k][0], A[k][1], A[k][2], A[k][3], b.x, b.y);
            }
        }
        __syncwarp();   // m reads done -> overlay out staging on A0/A1

        // ---- stage outputs (OB = A0, stride OSTR) ----
        float* OB = A0;
#pragma unroll
        for (int nt = 0; nt < 4; nt++) {
            int u = nt * 8 + 2 * m4;
            *(float2*)&OB[r4 * OSTR + u]       = make_float2(O0[4 * nt],     O0[4 * nt + 1]);
            *(float2*)&OB[(r4 + 8) * OSTR + u] = make_float2(O0[4 * nt + 2], O0[4 * nt + 3]);
#pragma unroll
            for (int k = 0; k < 3; k++) {
                int c = 32 + 3 * u + k;
                OB[r4 * OSTR + c]           = O[16 * k + 4 * nt];
                OB[r4 * OSTR + c + 3]       = O[16 * k + 4 * nt + 1];
                OB[(r4 + 8) * OSTR + c]     = O[16 * k + 4 * nt + 2];
                OB[(r4 + 8) * OSTR + c + 3] = O[16 * k + 4 * nt + 3];
            }
        }
        __syncwarp();
#pragma unroll
        for (int rr = 0; rr < 16; rr++)
            ((float4*)out)[(base + rr) * 32 + lane] = *(const float4*)&OB[rr * OSTR + 4 * lane];
        __syncwarp();
    }
}

// ---------------- launch ----------------
extern "C" void kernel_launch(void* const* d_in, const int* in_sizes, int n_in,
                              void* d_out, int out_size) {
    const float* x1a     = (const float*)d_in[0];
    const float* x1b     = (const float*)d_in[1];
    const float* x2      = (const float*)d_in[2];
    const float* scalars = (const float*)d_in[3];
    const float* w0      = (const float*)d_in[4];
    const float* w1      = (const float*)d_in[5];
    const float* w2      = (const float*)d_in[6];
    const float* w3      = (const float*)d_in[7];
    const float* Wl0     = (const float*)d_in[8];
    const float* Wl1     = (const float*)d_in[9];
    const float* Wm1     = (const float*)d_in[10];
    const float* Wm2     = (const float*)d_in[11];
    const float* Wm3     = (const float*)d_in[12];
    const float* Wf0     = (const float*)d_in[13];
    const float* Wf1     = (const float*)d_in[14];
    int n = in_sizes[0] / 128;

    cudaFuncSetAttribute(tp_mma_kernel, cudaFuncAttributeMaxDynamicSharedMemorySize, SMEM_BYTES);

    prep_kernel<<<112, 256>>>(w0, w1, w2, w3, Wl0, Wl1, Wm1, Wm2, Wm3, Wf0, Wf1);
    tp_mma_kernel<<<148, 32 * NWARP, SMEM_BYTES>>>(x1a, x1b, (const float4*)x2, scalars,
                                                   (float*)d_out, n);
}

// round 17
// speedup vs baseline: 1.2646x; 1.0400x over previous
#include <cuda_runtime.h>
#include <math.h>

typedef unsigned int u32;

// weight buffer (floats): w0,w2,w3,WB -> smem (critical TP loops);
// w1,WA,Wm1,Wm2,Wm3 stay in GLOBAL (L2-hot; batched or FMA-overlapped loops)
#define FB_W0  0
#define FB_W2  2048
#define FB_W3  4096
#define FB_WB  6144
#define FB_SM  8192                // floats copied to smem
#define FB_W1  8192
#define FB_WA  10240
#define FB_WM1 12288
#define FB_WM2 16384
#define FB_WM3 20480
#define FB_TOT 28672

#define NWARP  11
#define TSTR   68
#define TFL    (16 * TSTR)          // 1088
#define OSTR   132
#define ARENA  (4 * TFL)            // 4352 floats
#define SMEM_FLOATS (FB_SM + NWARP * ARENA)    // 8192 + 47872 = 56064
#define SMEM_BYTES  (SMEM_FLOATS * 4)          // 224256

__device__ float g_cst;
__device__ float g_wbuf[FB_TOT];

__device__ __forceinline__ u32 tf32(float f) {
    u32 u; asm("cvt.rna.tf32.f32 %0,%1;" : "=r"(u) : "f"(f)); return u;
}
__device__ __forceinline__ void mma_t(float* d, u32 a0, u32 a1, u32 a2, u32 a3,
                                      u32 b0, u32 b1) {
    asm("mma.sync.aligned.m16n8k8.row.col.f32.tf32.tf32.f32 "
        "{%0,%1,%2,%3},{%4,%5,%6,%7},{%8,%9},{%0,%1,%2,%3};"
        : "+f"(d[0]), "+f"(d[1]), "+f"(d[2]), "+f"(d[3])
        : "r"(a0), "r"(a1), "r"(a2), "r"(a3), "r"(b0), "r"(b1));
}

// acc[4*NT] += T[16x64] @ W(smem) ; single-tf32 A and W
template<int NT>
__device__ __forceinline__ void gemm16s(float* acc, const float* T, const float* W,
                                        int r4, int m4, int lane) {
#pragma unroll
    for (int k8 = 0; k8 < 8; k8++) {
        const float* ap = T + r4 * TSTR + k8 * 8 + m4;
        u32 a0 = tf32(ap[0]);
        u32 a1 = tf32(ap[8 * TSTR]);
        u32 a2 = tf32(ap[4]);
        u32 a3 = tf32(ap[8 * TSTR + 4]);
        const float* wp = W + k8 * NT * 64 + 2 * lane;
#pragma unroll
        for (int nt = 0; nt < NT; nt++) {
            uint2 b = *(const uint2*)(wp + nt * 64);
            mma_t(acc + 4 * nt, a0, a1, a2, a3, b.x, b.y);
        }
    }
}

// same but W read from GLOBAL via __ldg (L2-hot)
template<int NT>
__device__ __forceinline__ void gemm16g(float* acc, const float* T, const float* W,
                                        int r4, int m4, int lane) {
#pragma unroll
    for (int k8 = 0; k8 < 8; k8++) {
        const float* ap = T + r4 * TSTR + k8 * 8 + m4;
        u32 a0 = tf32(ap[0]);
        u32 a1 = tf32(ap[8 * TSTR]);
        u32 a2 = tf32(ap[4]);
        u32 a3 = tf32(ap[8 * TSTR + 4]);
        const float* wp = W + k8 * NT * 64 + 2 * lane;
#pragma unroll
        for (int nt = 0; nt < NT; nt++) {
            uint2 b = __ldg((const uint2*)(wp + nt * 64));
            mma_t(acc + 4 * nt, a0, a1, a2, a3, b.x, b.y);
        }
    }
}

// ---------------- prep ----------------
__global__ void prep_kernel(const float* __restrict__ w0, const float* __restrict__ w1,
                            const float* __restrict__ w2, const float* __restrict__ w3,
                            const float* __restrict__ Wl0, const float* __restrict__ Wl1,
                            const float* __restrict__ Wm1, const float* __restrict__ Wm2,
                            const float* __restrict__ Wm3,
                            const float* __restrict__ Wf0, const float* __restrict__ Wf1) {
    if (blockIdx.x == 0) {
        const int   N = 20000;
        const float h = 24.0f / 20000.0f;
        float local = 0.0f;
        for (int i = threadIdx.x; i <= N; i += blockDim.x) {
            float z   = -12.0f + h * (float)i;
            float s   = z / (1.0f + __expf(-z));
            float phi = __expf(-0.5f * z * z) * 0.3989422804014327f;
            float f   = s * s * phi;
            if (i == 0 || i == N) f *= 0.5f;
            local += f;
        }
        __shared__ float red[256];
        red[threadIdx.x] = local;
        __syncthreads();
        for (int s = 128; s > 0; s >>= 1) {
            if (threadIdx.x < s) red[threadIdx.x] += red[threadIdx.x + s];
            __syncthreads();
        }
        if (threadIdx.x == 0) g_cst = rsqrtf(red[0] * h);
    }

    int tid = blockIdx.x * blockDim.x + threadIdx.x;
    if (tid >= FB_TOT) return;
    const float INV_S3 = 0.57735026918962576f;
    const float WSCALE = 0.125f * 0.125f * 0.17677669529663687f;

    int mbase, N;
    if (tid < FB_WM1)          { mbase = (tid / 2048) * 2048; N = 32; }
    else if (tid < FB_WM2)     { mbase = FB_WM1; N = 64; }
    else if (tid < FB_WM3)     { mbase = FB_WM2; N = 64; }
    else                       { mbase = FB_WM3; N = 128; }
    int idx = tid - mbase;
    int g = idx >> 6, pos = idx & 63, l = pos >> 1, hh = pos & 1;
    int ntn = N >> 3, k8 = g / ntn, n8 = g % ntn;
    int row = k8 * 8 + (l & 3) + 4 * hh;   // K index
    int col = n8 * 8 + (l >> 2);           // N index

    float v;
    if (tid < FB_WM1) {
        int m = tid / 2048;   // 0:w0 1:w2 2:w3 3:WB 4:w1 5:WA
        if (m == 0)      v = w0[row * 32 + col];
        else if (m == 1) v = w2[row * 32 + col];
        else if (m == 2) v = w3[row * 32 + col];
        else if (m == 4) v = w1[row * 32 + col] * INV_S3;
        else {
            const float* L = (m == 3) ? Wl1 : Wl0;
            const float* F = (m == 3) ? Wf1 : Wf0;
            float acc = 0.0f;
            for (int w = 0; w < 32; w++) acc = fmaf(L[row * 32 + w], F[w * 32 + col], acc);
            v = acc * WSCALE;
        }
    }
    else if (tid < FB_WM2)     v = Wm1[row * 64 + col] * 0.125f;
    else if (tid < FB_WM3)     v = Wm2[row * 64 + col] * 0.125f;
    else                       v = Wm3[row * 128 + col] * 0.125f;
    g_wbuf[tid] = __uint_as_float(tf32(v));
}

// ---------------- main ----------------
__global__ __launch_bounds__(32 * NWARP, 1)
void tp_mma_kernel(const float* __restrict__ x1a, const float* __restrict__ x1b,
                   const float4* __restrict__ x2, const float* __restrict__ scalars,
                   float* __restrict__ out, int nrows) {
    extern __shared__ float smem[];
    {
        const float4* src = (const float4*)g_wbuf;
        float4* dst = (float4*)smem;
        for (int i = threadIdx.x; i < FB_SM / 4; i += 32 * NWARP) dst[i] = src[i];
    }
    __syncthreads();
    const float cst = g_cst;
    const float* w1g  = g_wbuf + FB_W1;
    const float* wag  = g_wbuf + FB_WA;
    const float* wm1g = g_wbuf + FB_WM1;
    const float* wm2g = g_wbuf + FB_WM2;
    const float* wm3g = g_wbuf + FB_WM3;

    const int lane = threadIdx.x & 31, wid = threadIdx.x >> 5;
    const int r4 = lane >> 2, m4 = lane & 3;

    float* A0 = smem + FB_SM + wid * ARENA;
    float* A1 = A0 + TFL;
    float* A2 = A1 + TFL;
    float* A3 = A2 + TFL;

    const int gw = blockIdx.x * NWARP + wid, gwn = gridDim.x * NWARP;
    const int ntiles = nrows >> 4;

    const int h_fid = lane;
    for (int t = gw; t < ntiles; t += gwn) {
        const int base = t * 16;

        // ---- tile start: issue ALL global loads (scalars, x1 tail, x1 head, y) ----
#pragma unroll
        for (int j = 0; j < 8; j++) {
            int row = r4 + 8 * (j & 1), f4 = m4 + 4 * (j >> 1);
            *(float4*)&A0[row * TSTR + 4 * f4] =
                ((const float4*)scalars)[(base + row) * 16 + f4];
        }
#pragma unroll
        for (int it = 0; it < 8; it++) {
            int sid = it * 32 + lane;
            int row = sid >> 4, within = sid & 15;
            int arr = within >> 3, q = within & 7;
            const float4* src = arr ? (const float4*)x1b : (const float4*)x1a;
            int p = (base + row) * 32 + 8 + 3 * q;
            float4 v0 = src[p], v1 = src[p + 1], v2 = src[p + 2];
            int off = row * TSTR + arr * 32 + 4 * q;
            *(float4*)&A1[off] = make_float4(v0.x, v0.w, v1.z, v2.y);
            *(float4*)&A2[off] = make_float4(v0.y, v1.x, v1.w, v2.z);
            *(float4*)&A3[off] = make_float4(v0.z, v1.y, v2.x, v2.w);
        }
        float4 hv[8];
#pragma unroll
        for (int it = 0; it < 8; it++) {
            int fid = it * 32 + h_fid;
            int row = fid >> 4, within = fid & 15;
            int arr = within >> 3, j = within & 7;
            const float4* src = arr ? (const float4*)x1b : (const float4*)x1a;
            hv[it] = __ldg(&src[(base + row) * 32 + j]);
        }
        float4 yA = __ldg(&x2[base + r4]);
        float4 yB = __ldg(&x2[base + r4 + 8]);
        const float y0A = yA.x, yA1 = yA.y, yA2 = yA.z, yA3 = yA.w;
        const float y0B = yB.x, yB1 = yB.y, yB2 = yB.z, yB3 = yB.w;
        __syncwarp();

        // ---- MLP GEMM1 -> silu -> GEMM2 -> silu -> GEMM3 (weights via L2) ----
        float h[32];
#pragma unroll
        for (int i = 0; i < 32; i++) h[i] = 0.f;
        gemm16g<8>(h, A0, wm1g, r4, m4, lane);
        __syncwarp();
#pragma unroll
        for (int nt = 0; nt < 8; nt++) {
            float a = h[4 * nt],     b = h[4 * nt + 1];
            float c = h[4 * nt + 2], d = h[4 * nt + 3];
            float2 lo = {cst * a / (1.f + __expf(-a)), cst * b / (1.f + __expf(-b))};
            float2 hi = {cst * c / (1.f + __expf(-c)), cst * d / (1.f + __expf(-d))};
            *(float2*)&A0[r4 * TSTR + nt * 8 + 2 * m4]       = lo;
            *(float2*)&A0[(r4 + 8) * TSTR + nt * 8 + 2 * m4] = hi;
        }
        __syncwarp();
#pragma unroll
        for (int i = 0; i < 32; i++) h[i] = 0.f;
        gemm16g<8>(h, A0, wm2g, r4, m4, lane);
        __syncwarp();
#pragma unroll
        for (int nt = 0; nt < 8; nt++) {
            float a = h[4 * nt],     b = h[4 * nt + 1];
            float c = h[4 * nt + 2], d = h[4 * nt + 3];
            float2 lo = {cst * a / (1.f + __expf(-a)), cst * b / (1.f + __expf(-b))};
            float2 hi = {cst * c / (1.f + __expf(-c)), cst * d / (1.f + __expf(-d))};
            *(float2*)&A0[r4 * TSTR + nt * 8 + 2 * m4]       = lo;
            *(float2*)&A0[(r4 + 8) * TSTR + nt * 8 + 2 * m4] = hi;
        }
        __syncwarp();
        float wt[64];
#pragma unroll
        for (int i = 0; i < 64; i++) wt[i] = 0.f;
        gemm16g<16>(wt, A0, wm3g, r4, m4, lane);
        __syncwarp();

        // ---- s0 head: registers -> A0 (STS only; LDG already done) ----
#pragma unroll
        for (int it = 0; it < 8; it++) {
            int fid = it * 32 + h_fid;
            int row = fid >> 4, within = fid & 15;
            int arr = within >> 3, j = within & 7;
            *(float4*)&A0[row * TSTR + arr * 32 + 4 * j] = hv[it];
        }
        __syncwarp();

        // ---- G4/G5: R0 = s0@w0, Pp = s0@w2 (shared A frags, smem weights) ----
        float R0[16], Pp[16], R1[16];
#pragma unroll
        for (int i = 0; i < 16; i++) { R0[i] = 0.f; Pp[i] = 0.f; R1[i] = 0.f; }
#pragma unroll
        for (int k8 = 0; k8 < 8; k8++) {
            const float* ap = A0 + r4 * TSTR + k8 * 8 + m4;
            u32 a0 = tf32(ap[0]);
            u32 a1 = tf32(ap[8 * TSTR]);
            u32 a2 = tf32(ap[4]);
            u32 a3 = tf32(ap[8 * TSTR + 4]);
            const float* w0p = smem + FB_W0 + k8 * 4 * 64 + 2 * lane;
            const float* w2p = smem + FB_W2 + k8 * 4 * 64 + 2 * lane;
#pragma unroll
            for (int nt = 0; nt < 4; nt++) {
                uint2 b0 = *(const uint2*)(w0p + nt * 64);
                mma_t(R0 + 4 * nt, a0, a1, a2, a3, b0.x, b0.y);
                uint2 b2 = *(const uint2*)(w2p + nt * 64);
                mma_t(Pp + 4 * nt, a0, a1, a2, a3, b2.x, b2.y);
            }
        }

        // ---- G6: R1 = t1@w1 (w1 via L2, overlapped by t1 FMA build) ----
#pragma unroll
        for (int k8 = 0; k8 < 8; k8++) {
            int o = r4 * TSTR + k8 * 8 + m4;
            float t0  = A1[o] * yA1 + A2[o] * yA2 + A3[o] * yA3;
            float t2  = A1[o + 4] * yA1 + A2[o + 4] * yA2 + A3[o + 4] * yA3;
            float t1v = A1[o + 8 * TSTR] * yB1 + A2[o + 8 * TSTR] * yB2 + A3[o + 8 * TSTR] * yB3;
            float t3  = A1[o + 8 * TSTR + 4] * yB1 + A2[o + 8 * TSTR + 4] * yB2 + A3[o + 8 * TSTR + 4] * yB3;
            u32 a0 = tf32(t0), a1 = tf32(t1v), a2 = tf32(t2), a3 = tf32(t3);
            const float* w1p = w1g + k8 * 4 * 64 + 2 * lane;
#pragma unroll
            for (int nt = 0; nt < 4; nt++) {
                uint2 b = __ldg((const uint2*)(w1p + nt * 64));
                mma_t(R1 + 4 * nt, a0, a1, a2, a3, b.x, b.y);
            }
        }
        __syncwarp();   // s0 reads done -> overlay m0 on A0

        // ---- m0 build -> A0 (float2 stores) ----
#pragma unroll
        for (int nt = 0; nt < 4; nt++) {
            int u = nt * 8 + 2 * m4;
            *(float2*)&A0[r4 * TSTR + u] =
                make_float2(y0A * R0[4 * nt] * wt[4 * nt], y0A * R0[4 * nt + 1] * wt[4 * nt + 1]);
            *(float2*)&A0[(r4 + 8) * TSTR + u] =
                make_float2(y0B * R0[4 * nt + 2] * wt[4 * nt + 2], y0B * R0[4 * nt + 3] * wt[4 * nt + 3]);
            int wi = 4 * (nt + 4);
            *(float2*)&A0[r4 * TSTR + 32 + u] =
                make_float2(R1[4 * nt] * wt[wi], R1[4 * nt + 1] * wt[wi + 1]);
            *(float2*)&A0[(r4 + 8) * TSTR + 32 + u] =
                make_float2(R1[4 * nt + 2] * wt[wi + 2], R1[4 * nt + 3] * wt[wi + 3]);
        }

        // ---- G7: Qk = s1k@w3 (smem, B shared across k) ----
        float Q[48];
#pragma unroll
        for (int i = 0; i < 48; i++) Q[i] = 0.f;
#pragma unroll
        for (int k8 = 0; k8 < 8; k8++) {
            u32 A[3][4];
#pragma unroll
            for (int k = 0; k < 3; k++) {
                const float* Tk = (k == 0) ? A1 : ((k == 1) ? A2 : A3);
                int o = r4 * TSTR + k8 * 8 + m4;
                A[k][0] = tf32(Tk[o]);
                A[k][1] = tf32(Tk[o + 8 * TSTR]);
                A[k][2] = tf32(Tk[o + 4]);
                A[k][3] = tf32(Tk[o + 8 * TSTR + 4]);
            }
            const float* w3p = smem + FB_W3 + k8 * 4 * 64 + 2 * lane;
#pragma unroll
            for (int nt = 0; nt < 4; nt++) {
                uint2 b = *(const uint2*)(w3p + nt * 64);
#pragma unroll
                for (int k = 0; k < 3; k++)
                    mma_t(Q + 16 * k + 4 * nt, A[k][0], A[k][1], A[k][2], A[k][3], b.x, b.y);
            }
        }
        __syncwarp();   // s1 reads done -> overlay m1k

        // ---- m1k build -> A1..A3 (float2 stores) ----
#pragma unroll
        for (int k = 0; k < 3; k++) {
            float* Tk = (k == 0) ? A1 : ((k == 1) ? A2 : A3);
            float ykA = (k == 0) ? yA1 : ((k == 1) ? yA2 : yA3);
            float ykB = (k == 0) ? yB1 : ((k == 1) ? yB2 : yB3);
#pragma unroll
            for (int nt = 0; nt < 4; nt++) {
                int wi = 4 * (nt + 8), wj = 4 * (nt + 12);
                int u = nt * 8 + 2 * m4;
                *(float2*)&Tk[r4 * TSTR + u] =
                    make_float2(ykA * Pp[4 * nt] * wt[wi], ykA * Pp[4 * nt + 1] * wt[wi + 1]);
                *(float2*)&Tk[(r4 + 8) * TSTR + u] =
                    make_float2(ykB * Pp[4 * nt + 2] * wt[wi + 2], ykB * Pp[4 * nt + 3] * wt[wi + 3]);
                *(float2*)&Tk[r4 * TSTR + 32 + u] =
                    make_float2(y0A * Q[16 * k + 4 * nt] * wt[wj], y0A * Q[16 * k + 4 * nt + 1] * wt[wj + 1]);
                *(float2*)&Tk[(r4 + 8) * TSTR + 32 + u] =
                    make_float2(y0B * Q[16 * k + 4 * nt + 2] * wt[wj + 2], y0B * Q[16 * k + 4 * nt + 3] * wt[wj + 3]);
            }
        }
        __syncwarp();

        // ---- G8: O0 = m0@WA (L2, batched) ; G9: Ok = m1k@WB (smem, B shared) ----
        float O0[16];
#pragma unroll
        for (int i = 0; i < 16; i++) O0[i] = 0.f;
        gemm16g<4>(O0, A0, wag, r4, m4, lane);

        float O[48];
#pragma unroll
        for (int i = 0; i < 48; i++) O[i] = 0.f;
#pragma unroll
        for (int k8 = 0; k8 < 8; k8++) {
            u32 A[3][4];
#pragma unroll
            for (int k = 0; k < 3; k++) {
                const float* Tk = (k == 0) ? A1 : ((k == 1) ? A2 : A3);
                int o = r4 * TSTR + k8 * 8 + m4;
                A[k][0] = tf32(Tk[o]);
                A[k][1] = tf32(Tk[o + 8 * TSTR]);
                A[k][2] = tf32(Tk[o + 4]);
                A[k][3] = tf32(Tk[o + 8 * TSTR + 4]);
            }
            const float* wbp = smem + FB_WB + k8 * 4 * 64 + 2 * lane;
#pragma unroll
            for (int nt = 0; nt < 4; nt++) {
                uint2 b = *(const uint2*)(wbp + nt * 64);
#pragma unroll
                for (int k = 0; k < 3; k++)
                    mma_t(O + 16 * k + 4 * nt, A[k][0], A[k][1], A[k][2], A[k][3], b.x, b.y);
            }
        }
        __syncwarp();   // m reads done -> overlay out staging on A0/A1

        // ---- stage outputs (OB = A0, stride OSTR) ----
        float* OB = A0;
#pragma unroll
        for (int nt = 0; nt < 4; nt++) {
            int u = nt * 8 + 2 * m4;
            *(float2*)&OB[r4 * OSTR + u]       = make_float2(O0[4 * nt],     O0[4 * nt + 1]);
            *(float2*)&OB[(r4 + 8) * OSTR + u] = make_float2(O0[4 * nt + 2], O0[4 * nt + 3]);
#pragma unroll
            for (int k = 0; k < 3; k++) {
                int c = 32 + 3 * u + k;
                OB[r4 * OSTR + c]           = O[16 * k + 4 * nt];
                OB[r4 * OSTR + c + 3]       = O[16 * k + 4 * nt + 1];
                OB[(r4 + 8) * OSTR + c]     = O[16 * k + 4 * nt + 2];
                OB[(r4 + 8) * OSTR + c + 3] = O[16 * k + 4 * nt + 3];
            }
        }
        __syncwarp();
#pragma unroll
        for (int rr = 0; rr < 16; rr++)
            ((float4*)out)[(base + rr) * 32 + lane] = *(const float4*)&OB[rr * OSTR + 4 * lane];
        __syncwarp();
    }
}

// ---------------- launch ----------------
extern "C" void kernel_launch(void* const* d_in, const int* in_sizes, int n_in,
                              void* d_out, int out_size) {
    const float* x1a     = (const float*)d_in[0];
    const float* x1b     = (const float*)d_in[1];
    const float* x2      = (const float*)d_in[2];
    const float* scalars = (const float*)d_in[3];
    const float* w0      = (const float*)d_in[4];
    const float* w1      = (const float*)d_in[5];
    const float* w2      = (const float*)d_in[6];
    const float* w3      = (const float*)d_in[7];
    const float* Wl0     = (const float*)d_in[8];
    const float* Wl1     = (const float*)d_in[9];
    const float* Wm1     = (const float*)d_in[10];
    const float* Wm2     = (const float*)d_in[11];
    const float* Wm3     = (const float*)d_in[12];
    const float* Wf0     = (const float*)d_in[13];
    const float* Wf1     = (const float*)d_in[14];
    int n = in_sizes[0] / 128;

    cudaFuncSetAttribute(tp_mma_kernel, cudaFuncAttributeMaxDynamicSharedMemorySize, SMEM_BYTES);

    prep_kernel<<<112, 256>>>(w0, w1, w2, w3, Wl0, Wl1, Wm1, Wm2, Wm3, Wf0, Wf1);
    tp_mma_kernel<<<148, 32 * NWARP, SMEM_BYTES>>>(x1a, x1b, (const float4*)x2, scalars,
                                                   (float*)d_out, n);
}